// round 5
// baseline (speedup 1.0000x reference)
#include <cuda_runtime.h>
#include <cuda_bf16.h>
#include <math.h>
#include <stdint.h>

#define B_   4
#define L_   4096
#define E_   1024
#define H_   16
#define HD_  64
#define M_   (B_*L_)    // 16384 rows
#define BH_  (B_*H_)    // 64 heads
#define EPS_ 1e-4f
#define KTOT 3072       // 3 * 1024 split segments
#define NCHUNK 8        // kv l-chunks

// ---------------- scratch (no allocations allowed) ----------------
__device__ __nv_bfloat16 g_x2[(size_t)M_*KTOT];     // [Ah|Ah|Al]
__device__ __nv_bfloat16 g_attn2[(size_t)M_*KTOT];  // [Ah|Ah|Al]
__device__ __nv_bfloat16 g_w2[4][(size_t)E_*KTOT];  // [Wh|Wl|Wh]
__device__ float g_q[(size_t)M_*E_];
__device__ float g_k[(size_t)M_*E_];
__device__ float g_v[(size_t)M_*E_];
__device__ float g_kvp[NCHUNK*BH_*128*HD_];
__device__ float g_ksump[NCHUNK*BH_*128];
__device__ float g_kv[BH_*128*HD_];
__device__ float g_ksum[BH_*128];

// ================= PTX helpers (sm_80-generic only!) =================
__device__ __forceinline__ uint32_t smem_u32(const void* p) {
    uint32_t a;
    asm("{ .reg .u64 t; cvta.to.shared.u64 t, %1; cvt.u32.u64 %0, t; }" : "=r"(a) : "l"(p));
    return a;
}
__device__ __forceinline__ void cp_async16(uint32_t saddr, const void* gaddr) {
    asm volatile("cp.async.cg.shared.global [%0], [%1], 16;" :: "r"(saddr), "l"(gaddr) : "memory");
}
__device__ __forceinline__ void cp_commit() {
    asm volatile("cp.async.commit_group;" ::: "memory");
}
template<int N> __device__ __forceinline__ void cp_wait_group() {
    asm volatile("cp.async.wait_group %0;" :: "n"(N) : "memory");
}
__device__ __forceinline__ void ldmatrix_x4(uint32_t* r, uint32_t addr) {
    asm volatile("ldmatrix.sync.aligned.m8n8.x4.shared.b16 {%0,%1,%2,%3}, [%4];"
        : "=r"(r[0]), "=r"(r[1]), "=r"(r[2]), "=r"(r[3]) : "r"(addr));
}
__device__ __forceinline__ void mma_bf16(float* c, const uint32_t* a, uint32_t b0, uint32_t b1) {
    asm volatile("mma.sync.aligned.m16n8k16.row.col.f32.bf16.bf16.f32 "
        "{%0,%1,%2,%3}, {%4,%5,%6,%7}, {%8,%9}, {%0,%1,%2,%3};"
        : "+f"(c[0]), "+f"(c[1]), "+f"(c[2]), "+f"(c[3])
        : "r"(a[0]), "r"(a[1]), "r"(a[2]), "r"(a[3]), "r"(b0), "r"(b1));
}
__device__ __forceinline__ uint32_t swz(uint32_t off) { return off ^ ((off >> 3) & 0x70); }

// ================= split conversion kernels =================
// AMODE=1: [hi|hi|lo] (activation side).  AMODE=0: [hi|lo|hi] (weight side).
template<int AMODE>
__global__ void split_kernel(const float* __restrict__ in, __nv_bfloat16* __restrict__ out, int rows)
{
    int idx = blockIdx.x * blockDim.x + threadIdx.x;          // one float4 per thread
    int total = rows * (E_ / 4);
    if (idx >= total) return;
    int row = idx >> 8;
    int c4  = (idx & 255) * 4;
    float4 v = *(const float4*)&in[(size_t)row * E_ + c4];
    __nv_bfloat16 hx = __float2bfloat16(v.x), hy = __float2bfloat16(v.y);
    __nv_bfloat16 hz = __float2bfloat16(v.z), hw = __float2bfloat16(v.w);
    __nv_bfloat16 lx = __float2bfloat16(v.x - __bfloat162float(hx));
    __nv_bfloat16 ly = __float2bfloat16(v.y - __bfloat162float(hy));
    __nv_bfloat16 lz = __float2bfloat16(v.z - __bfloat162float(hz));
    __nv_bfloat16 lw = __float2bfloat16(v.w - __bfloat162float(hw));
    union { __nv_bfloat16 b[4]; uint2 u; } Hh, Ll;
    Hh.b[0]=hx; Hh.b[1]=hy; Hh.b[2]=hz; Hh.b[3]=hw;
    Ll.b[0]=lx; Ll.b[1]=ly; Ll.b[2]=lz; Ll.b[3]=lw;
    __nv_bfloat16* ob = out + (size_t)row * KTOT + c4;
    *(uint2*)(ob)          = Hh.u;
    *(uint2*)(ob + 1024)   = AMODE ? Hh.u : Ll.u;
    *(uint2*)(ob + 2048)   = AMODE ? Ll.u : Hh.u;
}

// ================= HMMA GEMM =================
// C[M,1024] = A2[M,3072] x W2[1024,3072]^T (+bias, opt ReLU), bf16 in fp32 acc
// Tile 128x256x64, 8 warps (2x4), warp tile 64x64, mma.sync m16n8k16.
#define GBM 128
#define GBN 256
#define SLAB 64                 // bf16 K per slab = 128 bytes per row
#define NSLAB (KTOT/SLAB)       // 48
#define NSTG 4
#define A_BYTES (GBM*128)       // 16384
#define B_BYTES (GBN*128)       // 32768
#define STG_BYTES (A_BYTES+B_BYTES)  // 49152
#define GEMM_DSMEM (NSTG*STG_BYTES + 1024)

__device__ __forceinline__ void gemm_issue_loads(
    const __nv_bfloat16* ga, const __nv_bfloat16* gw,
    uint32_t base, int slab, int buf, int t)
{
    int k0 = slab * SLAB;
    uint32_t stA = base + buf * STG_BYTES;
    uint32_t stW = stA + A_BYTES;
    const __nv_bfloat16* gak = ga + k0;
    const __nv_bfloat16* gwk = gw + k0;
    #pragma unroll
    for (int j = 0; j < 4; j++) {
        int i = t + j * 256;            // 0..1023
        int row = i >> 3, c = i & 7;
        cp_async16(stA + swz(row * 128 + c * 16), gak + (size_t)row * KTOT + c * 8);
    }
    #pragma unroll
    for (int j = 0; j < 8; j++) {
        int i = t + j * 256;            // 0..2047
        int row = i >> 3, c = i & 7;
        cp_async16(stW + swz(row * 128 + c * 16), gwk + (size_t)row * KTOT + c * 8);
    }
    cp_commit();
}

template<int RELU>
__global__ __launch_bounds__(256, 1)
void gemm_mma(const __nv_bfloat16* __restrict__ A2, const __nv_bfloat16* __restrict__ W2,
              const float* __restrict__ bias, float* __restrict__ C)
{
    extern __shared__ char dsm[];
    const int t = threadIdx.x;
    const int wid = t >> 5, lane = t & 31;
    const int wm = wid & 1;             // 0..1  (64 rows each)
    const int wn = wid >> 1;            // 0..3  (64 cols each)
    const int bm = blockIdx.y * GBM;
    const int bn = blockIdx.x * GBN;

    uint32_t base = (smem_u32(dsm) + 1023u) & ~1023u;

    const __nv_bfloat16* ga = A2 + (size_t)bm * KTOT;
    const __nv_bfloat16* gw = W2 + (size_t)bn * KTOT;

    float acc[4][8][4];
    #pragma unroll
    for (int mi = 0; mi < 4; mi++)
        #pragma unroll
        for (int ni = 0; ni < 8; ni++)
            #pragma unroll
            for (int r = 0; r < 4; r++) acc[mi][ni][r] = 0.f;

    // prologue: stages 0..NSTG-2
    #pragma unroll
    for (int s = 0; s < NSTG - 1; s++) gemm_issue_loads(ga, gw, base, s, s, t);

    const int lrow = lane & 15;
    const int lhalf = (lane >> 4) * 16;   // byte offset within 32B k16 chunk

    for (int i = 0; i < NSLAB; i++) {
        cp_wait_group<NSTG - 2>();
        __syncthreads();
        if (i + NSTG - 1 < NSLAB)
            gemm_issue_loads(ga, gw, base, i + NSTG - 1, (i + NSTG - 1) % NSTG, t);
        else
            cp_commit();

        uint32_t sA = base + (i % NSTG) * STG_BYTES;
        uint32_t sB = sA + A_BYTES;

        #pragma unroll
        for (int kk = 0; kk < 4; kk++) {
            uint32_t a[4][4], b[4][4];
            #pragma unroll
            for (int mi = 0; mi < 4; mi++) {
                uint32_t off = (uint32_t)(wm * 64 + mi * 16 + lrow) * 128 + kk * 32 + lhalf;
                ldmatrix_x4(a[mi], sA + swz(off));
            }
            #pragma unroll
            for (int nb = 0; nb < 4; nb++) {
                uint32_t off = (uint32_t)(wn * 64 + nb * 16 + lrow) * 128 + kk * 32 + lhalf;
                ldmatrix_x4(b[nb], sB + swz(off));
            }
            #pragma unroll
            for (int mi = 0; mi < 4; mi++)
                #pragma unroll
                for (int ni = 0; ni < 8; ni++) {
                    int nb = ni >> 1, hi = ni & 1;
                    mma_bf16(acc[mi][ni], a[mi], b[nb][hi], b[nb][hi + 2]);
                }
        }
        __syncthreads();
    }

    // epilogue: bias (+ReLU) and store
    const int qrow = lane >> 2;          // 0..7
    const int qcol = (lane & 3) * 2;
    #pragma unroll
    for (int mi = 0; mi < 4; mi++) {
        int row0 = bm + wm * 64 + mi * 16 + qrow;
        #pragma unroll
        for (int ni = 0; ni < 8; ni++) {
            int col = bn + wn * 64 + ni * 8 + qcol;
            float2 bb = *(const float2*)&bias[col];
            float v0 = acc[mi][ni][0] + bb.x;
            float v1 = acc[mi][ni][1] + bb.y;
            float v2 = acc[mi][ni][2] + bb.x;
            float v3 = acc[mi][ni][3] + bb.y;
            if (RELU) {
                v0 = fmaxf(v0, 0.f); v1 = fmaxf(v1, 0.f);
                v2 = fmaxf(v2, 0.f); v3 = fmaxf(v3, 0.f);
            }
            *(float2*)&C[(size_t)row0 * E_ + col]       = make_float2(v0, v1);
            *(float2*)&C[(size_t)(row0 + 8) * E_ + col] = make_float2(v2, v3);
        }
    }
}

// ================= kv partial + reduce =================
__global__ __launch_bounds__(256)
void kv_partial(const float* __restrict__ k, const float* __restrict__ v)
{
    const int head = blockIdx.x;            // 0..63
    const int chunk = blockIdx.y;           // 0..7
    const int b = head / H_, h = head % H_;
    __shared__ float ks[32][128];
    __shared__ float vs[32][68];

    const int t  = threadIdx.x;
    const int tx = t & 15;
    const int ty = t >> 4;

    float acc[8][4];
    #pragma unroll
    for (int i = 0; i < 8; i++)
        #pragma unroll
        for (int j = 0; j < 4; j++) acc[i][j] = 0.f;
    float ksum_acc = 0.f;

    const int l_begin = chunk * (L_ / NCHUNK);
    const int l_end   = l_begin + (L_ / NCHUNK);

    for (int l0 = l_begin; l0 < l_end; l0 += 32) {
        #pragma unroll
        for (int r = 0; r < 2; r++) {
            int i   = t + r * 256;
            int row = i >> 4;
            int c4  = (i & 15) * 4;
            int l   = l0 + row;
            float ang = (float)M_PI * 0.5f * (float)(l + 1) / (float)L_;
            float s, c;
            sincosf(ang, &s, &c);
            size_t bse = ((size_t)(b * L_ + l)) * E_ + h * HD_ + c4;
            float4 kk4 = *(const float4*)&k[bse];
            ks[row][c4+0]    = s * kk4.x; ks[row][c4+1]    = s * kk4.y;
            ks[row][c4+2]    = s * kk4.z; ks[row][c4+3]    = s * kk4.w;
            ks[row][64+c4+0] = c * kk4.x; ks[row][64+c4+1] = c * kk4.y;
            ks[row][64+c4+2] = c * kk4.z; ks[row][64+c4+3] = c * kk4.w;
            float4 vv4 = *(const float4*)&v[bse];
            vs[row][c4+0] = vv4.x; vs[row][c4+1] = vv4.y;
            vs[row][c4+2] = vv4.z; vs[row][c4+3] = vv4.w;
        }
        __syncthreads();

        if (t < 128) {
            #pragma unroll
            for (int l = 0; l < 32; l++) ksum_acc += ks[l][t];
        }
        #pragma unroll 4
        for (int l = 0; l < 32; l++) {
            float a[8], bb[4];
            #pragma unroll
            for (int i = 0; i < 8; i++) a[i]  = ks[l][ty*8 + i];
            #pragma unroll
            for (int j = 0; j < 4; j++) bb[j] = vs[l][tx*4 + j];
            #pragma unroll
            for (int i = 0; i < 8; i++)
                #pragma unroll
                for (int j = 0; j < 4; j++)
                    acc[i][j] += a[i] * bb[j];
        }
        __syncthreads();
    }

    float* kvout = &g_kvp[((size_t)(chunk * BH_ + head)) * 128 * HD_];
    #pragma unroll
    for (int i = 0; i < 8; i++)
        #pragma unroll
        for (int j = 0; j < 4; j++)
            kvout[(ty*8 + i) * HD_ + tx*4 + j] = acc[i][j];
    if (t < 128) g_ksump[(chunk * BH_ + head) * 128 + t] = ksum_acc;
}

__global__ __launch_bounds__(256)
void kv_reduce()
{
    int head = blockIdx.x;
    int t = threadIdx.x;
    for (int e = t; e < 128 * HD_; e += 256) {
        float s = 0.f;
        #pragma unroll
        for (int c = 0; c < NCHUNK; c++)
            s += g_kvp[((size_t)(c * BH_ + head)) * 128 * HD_ + e];
        g_kv[(size_t)head * 128 * HD_ + e] = s;
    }
    if (t < 128) {
        float s = 0.f;
        #pragma unroll
        for (int c = 0; c < NCHUNK; c++)
            s += g_ksump[(c * BH_ + head) * 128 + t];
        g_ksum[head * 128 + t] = s;
    }
}

// ================= attn: out = z * q_ . kv, written directly as split bf16 ===
__global__ __launch_bounds__(256)
void attn_kernel(const float* __restrict__ q)
{
    const int ltile = blockIdx.x;           // 0..31
    const int head  = blockIdx.y;           // 0..63
    const int b = head / H_, h = head % H_;

    __shared__ float kvs[128][64];
    __shared__ float ksums[128];
    __shared__ float qrow[8][128];

    const int t = threadIdx.x;
    const int w = t >> 5, lane = t & 31;

    const float* kvg = &g_kv[(size_t)head * 128 * HD_];
    #pragma unroll
    for (int r = 0; r < 8; r++) {
        int i = t + r * 256;
        ((float4*)kvs)[i] = ((const float4*)kvg)[i];
    }
    if (t < 128) ksums[t] = g_ksum[head * 128 + t];
    __syncthreads();

    for (int it = 0; it < 16; it++) {
        int l = ltile * 128 + it * 8 + w;
        size_t qbase = ((size_t)(b * L_ + l)) * E_ + h * HD_;
        float ang = (float)M_PI * 0.5f * (float)(l + 1) / (float)L_;
        float s, c;
        sincosf(ang, &s, &c);
        float q0 = q[qbase + lane];
        float q1 = q[qbase + 32 + lane];
        qrow[w][lane]      = s * q0;
        qrow[w][32 + lane] = s * q1;
        qrow[w][64 + lane] = c * q0;
        qrow[w][96 + lane] = c * q1;
        __syncwarp();

        float zp = qrow[w][lane]      * ksums[lane]
                 + qrow[w][32 + lane] * ksums[32 + lane]
                 + qrow[w][64 + lane] * ksums[64 + lane]
                 + qrow[w][96 + lane] * ksums[96 + lane];
        #pragma unroll
        for (int o = 16; o > 0; o >>= 1) zp += __shfl_xor_sync(0xffffffffu, zp, o);
        float z = 1.f / fmaxf(zp, EPS_);

        float2 accum = make_float2(0.f, 0.f);
        #pragma unroll 8
        for (int d = 0; d < 128; d++) {
            float qd = qrow[w][d];
            float2 kv2 = *(const float2*)&kvs[d][lane * 2];
            accum.x += qd * kv2.x;
            accum.y += qd * kv2.y;
        }
        float ax = accum.x * z, ay = accum.y * z;
        __nv_bfloat16 hx = __float2bfloat16(ax), hy = __float2bfloat16(ay);
        __nv_bfloat16 lx = __float2bfloat16(ax - __bfloat162float(hx));
        __nv_bfloat16 ly = __float2bfloat16(ay - __bfloat162float(hy));
        union { __nv_bfloat16 b2[2]; uint32_t u; } Hh, Ll;
        Hh.b2[0] = hx; Hh.b2[1] = hy;
        Ll.b2[0] = lx; Ll.b2[1] = ly;
        __nv_bfloat16* ob = g_attn2 + ((size_t)(b * L_ + l)) * KTOT + h * HD_ + lane * 2;
        *(uint32_t*)(ob)        = Hh.u;
        *(uint32_t*)(ob + 1024) = Hh.u;
        *(uint32_t*)(ob + 2048) = Ll.u;
        __syncwarp();
    }
}

// ================= launcher =================
extern "C" void kernel_launch(void* const* d_in, const int* in_sizes, int n_in,
                              void* d_out, int out_size)
{
    const float* x  = (const float*)d_in[0];
    const float* Wq = (const float*)d_in[1];
    const float* bq = (const float*)d_in[2];
    const float* Wk = (const float*)d_in[3];
    const float* bk = (const float*)d_in[4];
    const float* Wv = (const float*)d_in[5];
    const float* bv = (const float*)d_in[6];
    const float* Wo = (const float*)d_in[7];
    const float* bo = (const float*)d_in[8];
    float* out = (float*)d_out;

    __nv_bfloat16 *x2, *attn2, *w2;
    float *q, *k, *v;
    cudaGetSymbolAddress((void**)&x2,    g_x2);
    cudaGetSymbolAddress((void**)&attn2, g_attn2);
    cudaGetSymbolAddress((void**)&w2,    g_w2);
    cudaGetSymbolAddress((void**)&q,     g_q);
    cudaGetSymbolAddress((void**)&k,     g_k);
    cudaGetSymbolAddress((void**)&v,     g_v);
    __nv_bfloat16* w2q = w2;
    __nv_bfloat16* w2k = w2 + (size_t)1 * E_ * KTOT;
    __nv_bfloat16* w2v = w2 + (size_t)2 * E_ * KTOT;
    __nv_bfloat16* w2o = w2 + (size_t)3 * E_ * KTOT;

    cudaFuncSetAttribute(gemm_mma<0>, cudaFuncAttributeMaxDynamicSharedMemorySize, GEMM_DSMEM);
    cudaFuncSetAttribute(gemm_mma<1>, cudaFuncAttributeMaxDynamicSharedMemorySize, GEMM_DSMEM);

    // split conversions
    split_kernel<1><<<M_ * (E_/4) / 256, 256>>>(x, x2, M_);
    split_kernel<0><<<E_ * (E_/4) / 256, 256>>>(Wq, w2q, E_);
    split_kernel<0><<<E_ * (E_/4) / 256, 256>>>(Wk, w2k, E_);
    split_kernel<0><<<E_ * (E_/4) / 256, 256>>>(Wv, w2v, E_);
    split_kernel<0><<<E_ * (E_/4) / 256, 256>>>(Wo, w2o, E_);

    dim3 gg(E_ / GBN, M_ / GBM);   // (4, 128)
    gemm_mma<1><<<gg, 256, GEMM_DSMEM>>>(x2, w2q, bq, q);
    gemm_mma<1><<<gg, 256, GEMM_DSMEM>>>(x2, w2k, bk, k);
    gemm_mma<0><<<gg, 256, GEMM_DSMEM>>>(x2, w2v, bv, v);

    kv_partial<<<dim3(BH_, NCHUNK), 256>>>(k, v);
    kv_reduce<<<BH_, 256>>>();
    attn_kernel<<<dim3(32, BH_), 256>>>(q);

    gemm_mma<0><<<gg, 256, GEMM_DSMEM>>>(attn2, w2o, bo, out);
}

// round 6
// speedup vs baseline: 1.4139x; 1.4139x over previous
#include <cuda_runtime.h>
#include <cuda_fp16.h>
#include <math.h>
#include <stdint.h>

#define B_   4
#define L_   4096
#define E_   1024
#define H_   16
#define HD_  64
#define M_   (B_*L_)    // 16384 rows
#define BH_  (B_*H_)    // 64 heads
#define EPS_ 1e-4f
#define KTOT 2048       // 2 * 1024 split segments (fp16 2-term)
#define NCHUNK 8        // kv l-chunks

// ---------------- scratch (no allocations allowed) ----------------
__device__ __half g_x2[(size_t)M_*KTOT];     // [Ah|Al]
__device__ __half g_attn2[(size_t)M_*KTOT];  // [Ah|Al]
__device__ __half g_w2[4][(size_t)E_*KTOT];  // [Wh|Wh]
__device__ float g_q[(size_t)M_*E_];
__device__ float g_k[(size_t)M_*E_];
__device__ float g_v[(size_t)M_*E_];
__device__ float g_kvp[NCHUNK*BH_*128*HD_];
__device__ float g_ksump[NCHUNK*BH_*128];
__device__ float g_kv[BH_*128*HD_];
__device__ float g_ksum[BH_*128];

// ================= PTX helpers (sm_80-generic only!) =================
__device__ __forceinline__ uint32_t smem_u32(const void* p) {
    uint32_t a;
    asm("{ .reg .u64 t; cvta.to.shared.u64 t, %1; cvt.u32.u64 %0, t; }" : "=r"(a) : "l"(p));
    return a;
}
__device__ __forceinline__ void cp_async16(uint32_t saddr, const void* gaddr) {
    asm volatile("cp.async.cg.shared.global [%0], [%1], 16;" :: "r"(saddr), "l"(gaddr) : "memory");
}
__device__ __forceinline__ void cp_commit() {
    asm volatile("cp.async.commit_group;" ::: "memory");
}
template<int N> __device__ __forceinline__ void cp_wait_group() {
    asm volatile("cp.async.wait_group %0;" :: "n"(N) : "memory");
}
__device__ __forceinline__ void ldmatrix_x4(uint32_t* r, uint32_t addr) {
    asm volatile("ldmatrix.sync.aligned.m8n8.x4.shared.b16 {%0,%1,%2,%3}, [%4];"
        : "=r"(r[0]), "=r"(r[1]), "=r"(r[2]), "=r"(r[3]) : "r"(addr));
}
__device__ __forceinline__ void mma_fp16(float* c, const uint32_t* a, uint32_t b0, uint32_t b1) {
    asm volatile("mma.sync.aligned.m16n8k16.row.col.f32.f16.f16.f32 "
        "{%0,%1,%2,%3}, {%4,%5,%6,%7}, {%8,%9}, {%0,%1,%2,%3};"
        : "+f"(c[0]), "+f"(c[1]), "+f"(c[2]), "+f"(c[3])
        : "r"(a[0]), "r"(a[1]), "r"(a[2]), "r"(a[3]), "r"(b0), "r"(b1));
}
__device__ __forceinline__ uint32_t swz(uint32_t off) { return off ^ ((off >> 3) & 0x70); }

// ================= split conversion kernels =================
// AMODE=1: [hi|lo] (activation side).  AMODE=0: [hi|hi] (weight side).
template<int AMODE>
__global__ void split_kernel(const float* __restrict__ in, __half* __restrict__ out, int rows)
{
    int idx = blockIdx.x * blockDim.x + threadIdx.x;          // one float4 per thread
    int total = rows * (E_ / 4);
    if (idx >= total) return;
    int row = idx >> 8;
    int c4  = (idx & 255) * 4;
    float4 v = *(const float4*)&in[(size_t)row * E_ + c4];
    __half hx = __float2half_rn(v.x), hy = __float2half_rn(v.y);
    __half hz = __float2half_rn(v.z), hw = __float2half_rn(v.w);
    union { __half b[4]; uint2 u; } Hh, Ll;
    Hh.b[0]=hx; Hh.b[1]=hy; Hh.b[2]=hz; Hh.b[3]=hw;
    if (AMODE) {
        Ll.b[0] = __float2half_rn(v.x - __half2float(hx));
        Ll.b[1] = __float2half_rn(v.y - __half2float(hy));
        Ll.b[2] = __float2half_rn(v.z - __half2float(hz));
        Ll.b[3] = __float2half_rn(v.w - __half2float(hw));
    } else {
        Ll.u = Hh.u;
    }
    __half* ob = out + (size_t)row * KTOT + c4;
    *(uint2*)(ob)        = Hh.u;
    *(uint2*)(ob + 1024) = Ll.u;
}

// ================= HMMA GEMM =================
// C[M,1024] = A2[M,2048] x W2[1024,2048]^T (+bias, opt ReLU), fp16 in fp32 acc
// Tile 128x128x64, 8 warps, warp tile 64x32, mma.sync m16n8k16. (R4 config)
#define GBM 128
#define GBN 128
#define SLAB 64                 // fp16 K per slab = 128 bytes per row
#define NSLAB (KTOT/SLAB)       // 32
#define NSTG 3
#define AB_BYTES (GBM*128)      // 16384 (A tile == B tile size)
#define STG_BYTES (2*AB_BYTES)  // 32768
#define GEMM_DSMEM (NSTG*STG_BYTES + 1024)

__device__ __forceinline__ void gemm_issue_loads(
    const __half* ga, const __half* gw,
    uint32_t base, int slab, int buf, int t)
{
    int k0 = slab * SLAB;
    uint32_t stA = base + buf * STG_BYTES;
    uint32_t stW = stA + AB_BYTES;
    const __half* gak = ga + k0;
    const __half* gwk = gw + k0;
    #pragma unroll
    for (int j = 0; j < 4; j++) {
        int i = t + j * 256;            // 0..1023
        int row = i >> 3, c = i & 7;
        cp_async16(stA + swz(row * 128 + c * 16), gak + (size_t)row * KTOT + c * 8);
    }
    #pragma unroll
    for (int j = 0; j < 4; j++) {
        int i = t + j * 256;
        int row = i >> 3, c = i & 7;
        cp_async16(stW + swz(row * 128 + c * 16), gwk + (size_t)row * KTOT + c * 8);
    }
    cp_commit();
}

template<int RELU>
__global__ __launch_bounds__(256, 2)
void gemm_mma(const __half* __restrict__ A2, const __half* __restrict__ W2,
              const float* __restrict__ bias, float* __restrict__ C)
{
    extern __shared__ char dsm[];
    const int t = threadIdx.x;
    const int wid = t >> 5, lane = t & 31;
    const int wm = wid >> 2;            // 0..1  (64 rows each)
    const int wn = wid & 3;             // 0..3  (32 cols each)
    const int bm = blockIdx.y * GBM;
    const int bn = blockIdx.x * GBN;

    uint32_t base = (smem_u32(dsm) + 1023u) & ~1023u;

    const __half* ga = A2 + (size_t)bm * KTOT;
    const __half* gw = W2 + (size_t)bn * KTOT;

    float acc[4][4][4];
    #pragma unroll
    for (int mi = 0; mi < 4; mi++)
        #pragma unroll
        for (int ni = 0; ni < 4; ni++)
            #pragma unroll
            for (int r = 0; r < 4; r++) acc[mi][ni][r] = 0.f;

    // prologue: stages 0..NSTG-2
    #pragma unroll
    for (int s = 0; s < NSTG - 1; s++) gemm_issue_loads(ga, gw, base, s, s, t);

    const int lrow = lane & 15;
    const int lhalf = (lane >> 4) * 16;   // byte offset within 32B k16 chunk

    for (int i = 0; i < NSLAB; i++) {
        cp_wait_group<NSTG - 2>();
        __syncthreads();
        if (i + NSTG - 1 < NSLAB)
            gemm_issue_loads(ga, gw, base, i + NSTG - 1, (i + NSTG - 1) % NSTG, t);
        else
            cp_commit();

        uint32_t sA = base + (i % NSTG) * STG_BYTES;
        uint32_t sB = sA + AB_BYTES;

        #pragma unroll
        for (int kk = 0; kk < 4; kk++) {
            uint32_t a[4][4], b[2][4];
            #pragma unroll
            for (int mi = 0; mi < 4; mi++) {
                uint32_t off = (uint32_t)(wm * 64 + mi * 16 + lrow) * 128 + kk * 32 + lhalf;
                ldmatrix_x4(a[mi], sA + swz(off));
            }
            #pragma unroll
            for (int nb = 0; nb < 2; nb++) {
                uint32_t off = (uint32_t)(wn * 32 + nb * 16 + lrow) * 128 + kk * 32 + lhalf;
                ldmatrix_x4(b[nb], sB + swz(off));
            }
            #pragma unroll
            for (int mi = 0; mi < 4; mi++)
                #pragma unroll
                for (int ni = 0; ni < 4; ni++) {
                    int nb = ni >> 1, hi = ni & 1;
                    mma_fp16(acc[mi][ni], a[mi], b[nb][hi], b[nb][hi + 2]);
                }
        }
        __syncthreads();
    }

    // epilogue: bias (+ReLU) and store
    const int qrow = lane >> 2;          // 0..7
    const int qcol = (lane & 3) * 2;
    #pragma unroll
    for (int mi = 0; mi < 4; mi++) {
        int row0 = bm + wm * 64 + mi * 16 + qrow;
        #pragma unroll
        for (int ni = 0; ni < 4; ni++) {
            int col = bn + wn * 32 + ni * 8 + qcol;
            float2 bb = *(const float2*)&bias[col];
            float v0 = acc[mi][ni][0] + bb.x;
            float v1 = acc[mi][ni][1] + bb.y;
            float v2 = acc[mi][ni][2] + bb.x;
            float v3 = acc[mi][ni][3] + bb.y;
            if (RELU) {
                v0 = fmaxf(v0, 0.f); v1 = fmaxf(v1, 0.f);
                v2 = fmaxf(v2, 0.f); v3 = fmaxf(v3, 0.f);
            }
            *(float2*)&C[(size_t)row0 * E_ + col]       = make_float2(v0, v1);
            *(float2*)&C[(size_t)(row0 + 8) * E_ + col] = make_float2(v2, v3);
        }
    }
}

// ================= kv partial + reduce =================
__global__ __launch_bounds__(256)
void kv_partial(const float* __restrict__ k, const float* __restrict__ v)
{
    const int head = blockIdx.x;            // 0..63
    const int chunk = blockIdx.y;           // 0..7
    const int b = head / H_, h = head % H_;
    __shared__ float ks[32][128];
    __shared__ float vs[32][68];

    const int t  = threadIdx.x;
    const int tx = t & 15;
    const int ty = t >> 4;

    float acc[8][4];
    #pragma unroll
    for (int i = 0; i < 8; i++)
        #pragma unroll
        for (int j = 0; j < 4; j++) acc[i][j] = 0.f;
    float ksum_acc = 0.f;

    const int l_begin = chunk * (L_ / NCHUNK);
    const int l_end   = l_begin + (L_ / NCHUNK);

    for (int l0 = l_begin; l0 < l_end; l0 += 32) {
        #pragma unroll
        for (int r = 0; r < 2; r++) {
            int i   = t + r * 256;
            int row = i >> 4;
            int c4  = (i & 15) * 4;
            int l   = l0 + row;
            float ang = (float)M_PI * 0.5f * (float)(l + 1) / (float)L_;
            float s, c;
            sincosf(ang, &s, &c);
            size_t bse = ((size_t)(b * L_ + l)) * E_ + h * HD_ + c4;
            float4 kk4 = *(const float4*)&k[bse];
            ks[row][c4+0]    = s * kk4.x; ks[row][c4+1]    = s * kk4.y;
            ks[row][c4+2]    = s * kk4.z; ks[row][c4+3]    = s * kk4.w;
            ks[row][64+c4+0] = c * kk4.x; ks[row][64+c4+1] = c * kk4.y;
            ks[row][64+c4+2] = c * kk4.z; ks[row][64+c4+3] = c * kk4.w;
            float4 vv4 = *(const float4*)&v[bse];
            vs[row][c4+0] = vv4.x; vs[row][c4+1] = vv4.y;
            vs[row][c4+2] = vv4.z; vs[row][c4+3] = vv4.w;
        }
        __syncthreads();

        if (t < 128) {
            #pragma unroll
            for (int l = 0; l < 32; l++) ksum_acc += ks[l][t];
        }
        #pragma unroll 4
        for (int l = 0; l < 32; l++) {
            float a[8], bb[4];
            #pragma unroll
            for (int i = 0; i < 8; i++) a[i]  = ks[l][ty*8 + i];
            #pragma unroll
            for (int j = 0; j < 4; j++) bb[j] = vs[l][tx*4 + j];
            #pragma unroll
            for (int i = 0; i < 8; i++)
                #pragma unroll
                for (int j = 0; j < 4; j++)
                    acc[i][j] += a[i] * bb[j];
        }
        __syncthreads();
    }

    float* kvout = &g_kvp[((size_t)(chunk * BH_ + head)) * 128 * HD_];
    #pragma unroll
    for (int i = 0; i < 8; i++)
        #pragma unroll
        for (int j = 0; j < 4; j++)
            kvout[(ty*8 + i) * HD_ + tx*4 + j] = acc[i][j];
    if (t < 128) g_ksump[(chunk * BH_ + head) * 128 + t] = ksum_acc;
}

__global__ __launch_bounds__(256)
void kv_reduce()
{
    int head = blockIdx.x;
    int t = threadIdx.x;
    for (int e = t; e < 128 * HD_; e += 256) {
        float s = 0.f;
        #pragma unroll
        for (int c = 0; c < NCHUNK; c++)
            s += g_kvp[((size_t)(c * BH_ + head)) * 128 * HD_ + e];
        g_kv[(size_t)head * 128 * HD_ + e] = s;
    }
    if (t < 128) {
        float s = 0.f;
        #pragma unroll
        for (int c = 0; c < NCHUNK; c++)
            s += g_ksump[(c * BH_ + head) * 128 + t];
        g_ksum[head * 128 + t] = s;
    }
}

// ================= attn: out = z * q_ . kv, written directly as split fp16 ===
__global__ __launch_bounds__(256)
void attn_kernel(const float* __restrict__ q)
{
    const int ltile = blockIdx.x;           // 0..31
    const int head  = blockIdx.y;           // 0..63
    const int b = head / H_, h = head % H_;

    __shared__ float kvs[128][64];
    __shared__ float ksums[128];
    __shared__ float qrow[8][128];

    const int t = threadIdx.x;
    const int w = t >> 5, lane = t & 31;

    const float* kvg = &g_kv[(size_t)head * 128 * HD_];
    #pragma unroll
    for (int r = 0; r < 8; r++) {
        int i = t + r * 256;
        ((float4*)kvs)[i] = ((const float4*)kvg)[i];
    }
    if (t < 128) ksums[t] = g_ksum[head * 128 + t];
    __syncthreads();

    for (int it = 0; it < 16; it++) {
        int l = ltile * 128 + it * 8 + w;
        size_t qbase = ((size_t)(b * L_ + l)) * E_ + h * HD_;
        float ang = (float)M_PI * 0.5f * (float)(l + 1) / (float)L_;
        float s, c;
        sincosf(ang, &s, &c);
        float q0 = q[qbase + lane];
        float q1 = q[qbase + 32 + lane];
        qrow[w][lane]      = s * q0;
        qrow[w][32 + lane] = s * q1;
        qrow[w][64 + lane] = c * q0;
        qrow[w][96 + lane] = c * q1;
        __syncwarp();

        float zp = qrow[w][lane]      * ksums[lane]
                 + qrow[w][32 + lane] * ksums[32 + lane]
                 + qrow[w][64 + lane] * ksums[64 + lane]
                 + qrow[w][96 + lane] * ksums[96 + lane];
        #pragma unroll
        for (int o = 16; o > 0; o >>= 1) zp += __shfl_xor_sync(0xffffffffu, zp, o);
        float z = 1.f / fmaxf(zp, EPS_);

        float2 accum = make_float2(0.f, 0.f);
        #pragma unroll 8
        for (int d = 0; d < 128; d++) {
            float qd = qrow[w][d];
            float2 kv2 = *(const float2*)&kvs[d][lane * 2];
            accum.x += qd * kv2.x;
            accum.y += qd * kv2.y;
        }
        float ax = accum.x * z, ay = accum.y * z;
        __half hx = __float2half_rn(ax), hy = __float2half_rn(ay);
        __half lx = __float2half_rn(ax - __half2float(hx));
        __half ly = __float2half_rn(ay - __half2float(hy));
        union { __half b2[2]; uint32_t u; } Hh, Ll;
        Hh.b2[0] = hx; Hh.b2[1] = hy;
        Ll.b2[0] = lx; Ll.b2[1] = ly;
        __half* ob = g_attn2 + ((size_t)(b * L_ + l)) * KTOT + h * HD_ + lane * 2;
        *(uint32_t*)(ob)        = Hh.u;
        *(uint32_t*)(ob + 1024) = Ll.u;
        __syncwarp();
    }
}

// ================= launcher =================
extern "C" void kernel_launch(void* const* d_in, const int* in_sizes, int n_in,
                              void* d_out, int out_size)
{
    const float* x  = (const float*)d_in[0];
    const float* Wq = (const float*)d_in[1];
    const float* bq = (const float*)d_in[2];
    const float* Wk = (const float*)d_in[3];
    const float* bk = (const float*)d_in[4];
    const float* Wv = (const float*)d_in[5];
    const float* bv = (const float*)d_in[6];
    const float* Wo = (const float*)d_in[7];
    const float* bo = (const float*)d_in[8];
    float* out = (float*)d_out;

    __half *x2, *attn2, *w2;
    float *q, *k, *v;
    cudaGetSymbolAddress((void**)&x2,    g_x2);
    cudaGetSymbolAddress((void**)&attn2, g_attn2);
    cudaGetSymbolAddress((void**)&w2,    g_w2);
    cudaGetSymbolAddress((void**)&q,     g_q);
    cudaGetSymbolAddress((void**)&k,     g_k);
    cudaGetSymbolAddress((void**)&v,     g_v);
    __half* w2q = w2;
    __half* w2k = w2 + (size_t)1 * E_ * KTOT;
    __half* w2v = w2 + (size_t)2 * E_ * KTOT;
    __half* w2o = w2 + (size_t)3 * E_ * KTOT;

    cudaFuncSetAttribute(gemm_mma<0>, cudaFuncAttributeMaxDynamicSharedMemorySize, GEMM_DSMEM);
    cudaFuncSetAttribute(gemm_mma<1>, cudaFuncAttributeMaxDynamicSharedMemorySize, GEMM_DSMEM);

    // split conversions
    split_kernel<1><<<M_ * (E_/4) / 256, 256>>>(x, x2, M_);
    split_kernel<0><<<E_ * (E_/4) / 256, 256>>>(Wq, w2q, E_);
    split_kernel<0><<<E_ * (E_/4) / 256, 256>>>(Wk, w2k, E_);
    split_kernel<0><<<E_ * (E_/4) / 256, 256>>>(Wv, w2v, E_);
    split_kernel<0><<<E_ * (E_/4) / 256, 256>>>(Wo, w2o, E_);

    dim3 gg(E_ / GBN, M_ / GBM);   // (8, 128)
    gemm_mma<1><<<gg, 256, GEMM_DSMEM>>>(x2, w2q, bq, q);
    gemm_mma<1><<<gg, 256, GEMM_DSMEM>>>(x2, w2k, bk, k);
    gemm_mma<0><<<gg, 256, GEMM_DSMEM>>>(x2, w2v, bv, v);

    kv_partial<<<dim3(BH_, NCHUNK), 256>>>(k, v);
    kv_reduce<<<BH_, 256>>>();
    attn_kernel<<<dim3(32, BH_), 256>>>(q);

    gemm_mma<0><<<gg, 256, GEMM_DSMEM>>>(attn2, w2o, bo, out);
}

// round 7
// speedup vs baseline: 1.6280x; 1.1514x over previous
#include <cuda_runtime.h>
#include <cuda_fp16.h>
#include <math.h>
#include <stdint.h>

#define B_   4
#define L_   4096
#define E_   1024
#define H_   16
#define HD_  64
#define M_   (B_*L_)    // 16384 rows
#define BH_  (B_*H_)    // 64 heads
#define EPS_ 1e-4f
#define KTOT 2048       // 2 * 1024 split segments (fp16 2-term)
#define NCHUNK 8        // kv l-chunks

// ---------------- scratch (no allocations allowed) ----------------
__device__ __half g_x2[(size_t)M_*KTOT];     // [Ah|Al]
__device__ __half g_attn2[(size_t)M_*KTOT];  // [Ah|Al]
__device__ __half g_w2[4][(size_t)E_*KTOT];  // [Wh|Wh]
__device__ float g_q[(size_t)M_*E_];
__device__ float g_k[(size_t)M_*E_];
__device__ float g_v[(size_t)M_*E_];
__device__ float g_kvp[NCHUNK*BH_*128*HD_];
__device__ float g_ksump[NCHUNK*BH_*128];
__device__ float g_ksum[BH_*128];
__device__ __half g_kvt2[(size_t)BH_*64*256];  // per head: [64 m][kvh(128) | kvl(128)]

// ================= PTX helpers (sm_80-generic only!) =================
__device__ __forceinline__ uint32_t smem_u32(const void* p) {
    uint32_t a;
    asm("{ .reg .u64 t; cvta.to.shared.u64 t, %1; cvt.u32.u64 %0, t; }" : "=r"(a) : "l"(p));
    return a;
}
__device__ __forceinline__ void cp_async16(uint32_t saddr, const void* gaddr) {
    asm volatile("cp.async.cg.shared.global [%0], [%1], 16;" :: "r"(saddr), "l"(gaddr) : "memory");
}
__device__ __forceinline__ void cp_commit() {
    asm volatile("cp.async.commit_group;" ::: "memory");
}
template<int N> __device__ __forceinline__ void cp_wait_group() {
    asm volatile("cp.async.wait_group %0;" :: "n"(N) : "memory");
}
__device__ __forceinline__ void ldmatrix_x4(uint32_t* r, uint32_t addr) {
    asm volatile("ldmatrix.sync.aligned.m8n8.x4.shared.b16 {%0,%1,%2,%3}, [%4];"
        : "=r"(r[0]), "=r"(r[1]), "=r"(r[2]), "=r"(r[3]) : "r"(addr));
}
__device__ __forceinline__ void mma_fp16(float* c, const uint32_t* a, uint32_t b0, uint32_t b1) {
    asm volatile("mma.sync.aligned.m16n8k16.row.col.f32.f16.f16.f32 "
        "{%0,%1,%2,%3}, {%4,%5,%6,%7}, {%8,%9}, {%0,%1,%2,%3};"
        : "+f"(c[0]), "+f"(c[1]), "+f"(c[2]), "+f"(c[3])
        : "r"(a[0]), "r"(a[1]), "r"(a[2]), "r"(a[3]), "r"(b0), "r"(b1));
}
__device__ __forceinline__ uint32_t swz(uint32_t off) { return off ^ ((off >> 3) & 0x70); }

// ================= split conversion kernels =================
// AMODE=1: [hi|lo] (activation side).  AMODE=0: [hi|hi] (weight side).
template<int AMODE>
__global__ void split_kernel(const float* __restrict__ in, __half* __restrict__ out, int rows)
{
    int idx = blockIdx.x * blockDim.x + threadIdx.x;          // one float4 per thread
    int total = rows * (E_ / 4);
    if (idx >= total) return;
    int row = idx >> 8;
    int c4  = (idx & 255) * 4;
    float4 v = *(const float4*)&in[(size_t)row * E_ + c4];
    __half hx = __float2half_rn(v.x), hy = __float2half_rn(v.y);
    __half hz = __float2half_rn(v.z), hw = __float2half_rn(v.w);
    union { __half b[4]; uint2 u; } Hh, Ll;
    Hh.b[0]=hx; Hh.b[1]=hy; Hh.b[2]=hz; Hh.b[3]=hw;
    if (AMODE) {
        Ll.b[0] = __float2half_rn(v.x - __half2float(hx));
        Ll.b[1] = __float2half_rn(v.y - __half2float(hy));
        Ll.b[2] = __float2half_rn(v.z - __half2float(hz));
        Ll.b[3] = __float2half_rn(v.w - __half2float(hw));
    } else {
        Ll.u = Hh.u;
    }
    __half* ob = out + (size_t)row * KTOT + c4;
    *(uint2*)(ob)        = Hh.u;
    *(uint2*)(ob + 1024) = Ll.u;
}

// ================= HMMA GEMM =================
// Tile 128x128x64, 8 warps, warp tile 64x32, mma.sync m16n8k16.
#define GBM 128
#define GBN 128
#define SLAB 64                 // fp16 K per slab = 128 bytes per row
#define NSLAB (KTOT/SLAB)       // 32
#define NSTG 3
#define AB_BYTES (GBM*128)      // 16384 (A tile == B tile size)
#define STG_BYTES (2*AB_BYTES)  // 32768
#define GEMM_DSMEM (NSTG*STG_BYTES + 1024)

__device__ __forceinline__ void gemm_issue_loads(
    const __half* ga, const __half* gw,
    uint32_t base, int slab, int buf, int t)
{
    int k0 = slab * SLAB;
    uint32_t stA = base + buf * STG_BYTES;
    uint32_t stW = stA + AB_BYTES;
    const __half* gak = ga + k0;
    const __half* gwk = gw + k0;
    #pragma unroll
    for (int j = 0; j < 4; j++) {
        int i = t + j * 256;            // 0..1023
        int row = i >> 3, c = i & 7;
        cp_async16(stA + swz(row * 128 + c * 16), gak + (size_t)row * KTOT + c * 8);
    }
    #pragma unroll
    for (int j = 0; j < 4; j++) {
        int i = t + j * 256;
        int row = i >> 3, c = i & 7;
        cp_async16(stW + swz(row * 128 + c * 16), gwk + (size_t)row * KTOT + c * 8);
    }
    cp_commit();
}

// Core mainloop shared by both GEMM kernels; results left in acc.
struct GemmFrag { float acc[4][4][4]; };

__device__ __forceinline__ void gemm_mainloop(
    const __half* ga, const __half* gw, uint32_t base, int t, GemmFrag& F)
{
    const int wid = t >> 5, lane = t & 31;
    const int wm = wid >> 2;
    const int wn = wid & 3;
    #pragma unroll
    for (int mi = 0; mi < 4; mi++)
        #pragma unroll
        for (int ni = 0; ni < 4; ni++)
            #pragma unroll
            for (int r = 0; r < 4; r++) F.acc[mi][ni][r] = 0.f;

    #pragma unroll
    for (int s = 0; s < NSTG - 1; s++) gemm_issue_loads(ga, gw, base, s, s, t);

    const int lrow = lane & 15;
    const int lhalf = (lane >> 4) * 16;

    for (int i = 0; i < NSLAB; i++) {
        cp_wait_group<NSTG - 2>();
        __syncthreads();
        if (i + NSTG - 1 < NSLAB)
            gemm_issue_loads(ga, gw, base, i + NSTG - 1, (i + NSTG - 1) % NSTG, t);
        else
            cp_commit();

        uint32_t sA = base + (i % NSTG) * STG_BYTES;
        uint32_t sB = sA + AB_BYTES;

        #pragma unroll
        for (int kk = 0; kk < 4; kk++) {
            uint32_t a[4][4], b[2][4];
            #pragma unroll
            for (int mi = 0; mi < 4; mi++) {
                uint32_t off = (uint32_t)(wm * 64 + mi * 16 + lrow) * 128 + kk * 32 + lhalf;
                ldmatrix_x4(a[mi], sA + swz(off));
            }
            #pragma unroll
            for (int nb = 0; nb < 2; nb++) {
                uint32_t off = (uint32_t)(wn * 32 + nb * 16 + lrow) * 128 + kk * 32 + lhalf;
                ldmatrix_x4(b[nb], sB + swz(off));
            }
            #pragma unroll
            for (int mi = 0; mi < 4; mi++)
                #pragma unroll
                for (int ni = 0; ni < 4; ni++) {
                    int nb = ni >> 1, hi = ni & 1;
                    mma_fp16(F.acc[mi][ni], a[mi], b[nb][hi], b[nb][hi + 2]);
                }
        }
        __syncthreads();
    }
}

__device__ __forceinline__ void gemm_epilogue(
    GemmFrag& F, const float* bias, float* C, int bm, int cn, bool relu, int t)
{
    const int wid = t >> 5, lane = t & 31;
    const int wm = wid >> 2, wn = wid & 3;
    const int qrow = lane >> 2;
    const int qcol = (lane & 3) * 2;
    #pragma unroll
    for (int mi = 0; mi < 4; mi++) {
        int row0 = bm + wm * 64 + mi * 16 + qrow;
        #pragma unroll
        for (int ni = 0; ni < 4; ni++) {
            int col = cn + wn * 32 + ni * 8 + qcol;
            float2 bb = *(const float2*)&bias[col];
            float v0 = F.acc[mi][ni][0] + bb.x;
            float v1 = F.acc[mi][ni][1] + bb.y;
            float v2 = F.acc[mi][ni][2] + bb.x;
            float v3 = F.acc[mi][ni][3] + bb.y;
            if (relu) {
                v0 = fmaxf(v0, 0.f); v1 = fmaxf(v1, 0.f);
                v2 = fmaxf(v2, 0.f); v3 = fmaxf(v3, 0.f);
            }
            *(float2*)&C[(size_t)row0 * E_ + col]       = make_float2(v0, v1);
            *(float2*)&C[(size_t)(row0 + 8) * E_ + col] = make_float2(v2, v3);
        }
    }
}

// Merged Q/K/V projection: W2all = [Wq2; Wk2; Wv2] rows 0..3071
__global__ __launch_bounds__(256, 2)
void gemm_qkv(const __half* __restrict__ A2, const __half* __restrict__ W2all,
              const float* __restrict__ bq, const float* __restrict__ bk,
              const float* __restrict__ bv,
              float* __restrict__ qp, float* __restrict__ kp, float* __restrict__ vp)
{
    extern __shared__ char dsm[];
    const int t = threadIdx.x;
    const int bm = blockIdx.y * GBM;
    const int bnG = blockIdx.x * GBN;          // 0..2944
    const int seg = bnG >> 10;                 // 0=q 1=k 2=v
    const int cn = bnG & 1023;

    uint32_t base = (smem_u32(dsm) + 1023u) & ~1023u;
    const __half* ga = A2 + (size_t)bm * KTOT;
    const __half* gw = W2all + (size_t)bnG * KTOT;

    GemmFrag F;
    gemm_mainloop(ga, gw, base, t, F);

    const float* bias = (seg == 0) ? bq : (seg == 1) ? bk : bv;
    float* C = (seg == 0) ? qp : (seg == 1) ? kp : vp;
    gemm_epilogue(F, bias, C, bm, cn, seg < 2, t);
}

// Single-output GEMM (used for Wo)
__global__ __launch_bounds__(256, 2)
void gemm_mma(const __half* __restrict__ A2, const __half* __restrict__ W2,
              const float* __restrict__ bias, float* __restrict__ C)
{
    extern __shared__ char dsm[];
    const int t = threadIdx.x;
    const int bm = blockIdx.y * GBM;
    const int bn = blockIdx.x * GBN;

    uint32_t base = (smem_u32(dsm) + 1023u) & ~1023u;
    const __half* ga = A2 + (size_t)bm * KTOT;
    const __half* gw = W2 + (size_t)bn * KTOT;

    GemmFrag F;
    gemm_mainloop(ga, gw, base, t, F);
    gemm_epilogue(F, bias, C, bm, bn, false, t);
}

// ================= kv partial + reduce =================
__global__ __launch_bounds__(256)
void kv_partial(const float* __restrict__ k, const float* __restrict__ v)
{
    const int head = blockIdx.x;            // 0..63
    const int chunk = blockIdx.y;           // 0..7
    const int b = head / H_, h = head % H_;
    __shared__ float ks[32][128];
    __shared__ float vs[32][68];

    const int t  = threadIdx.x;
    const int tx = t & 15;
    const int ty = t >> 4;

    float acc[8][4];
    #pragma unroll
    for (int i = 0; i < 8; i++)
        #pragma unroll
        for (int j = 0; j < 4; j++) acc[i][j] = 0.f;
    float ksum_acc = 0.f;

    const int l_begin = chunk * (L_ / NCHUNK);
    const int l_end   = l_begin + (L_ / NCHUNK);

    for (int l0 = l_begin; l0 < l_end; l0 += 32) {
        #pragma unroll
        for (int r = 0; r < 2; r++) {
            int i   = t + r * 256;
            int row = i >> 4;
            int c4  = (i & 15) * 4;
            int l   = l0 + row;
            float ang = (float)M_PI * 0.5f * (float)(l + 1) / (float)L_;
            float s, c;
            sincosf(ang, &s, &c);
            size_t bse = ((size_t)(b * L_ + l)) * E_ + h * HD_ + c4;
            float4 kk4 = *(const float4*)&k[bse];
            ks[row][c4+0]    = s * kk4.x; ks[row][c4+1]    = s * kk4.y;
            ks[row][c4+2]    = s * kk4.z; ks[row][c4+3]    = s * kk4.w;
            ks[row][64+c4+0] = c * kk4.x; ks[row][64+c4+1] = c * kk4.y;
            ks[row][64+c4+2] = c * kk4.z; ks[row][64+c4+3] = c * kk4.w;
            float4 vv4 = *(const float4*)&v[bse];
            vs[row][c4+0] = vv4.x; vs[row][c4+1] = vv4.y;
            vs[row][c4+2] = vv4.z; vs[row][c4+3] = vv4.w;
        }
        __syncthreads();

        if (t < 128) {
            #pragma unroll
            for (int l = 0; l < 32; l++) ksum_acc += ks[l][t];
        }
        #pragma unroll 4
        for (int l = 0; l < 32; l++) {
            float a[8], bb[4];
            #pragma unroll
            for (int i = 0; i < 8; i++) a[i]  = ks[l][ty*8 + i];
            #pragma unroll
            for (int j = 0; j < 4; j++) bb[j] = vs[l][tx*4 + j];
            #pragma unroll
            for (int i = 0; i < 8; i++)
                #pragma unroll
                for (int j = 0; j < 4; j++)
                    acc[i][j] += a[i] * bb[j];
        }
        __syncthreads();
    }

    float* kvout = &g_kvp[((size_t)(chunk * BH_ + head)) * 128 * HD_];
    #pragma unroll
    for (int i = 0; i < 8; i++)
        #pragma unroll
        for (int j = 0; j < 4; j++)
            kvout[(ty*8 + i) * HD_ + tx*4 + j] = acc[i][j];
    if (t < 128) g_ksump[(chunk * BH_ + head) * 128 + t] = ksum_acc;
}

// Reduce partials; emit transposed fp16 2-term kv: g_kvt2[head][m][ kvh(d) | kvl(d) ]
__global__ __launch_bounds__(256)
void kv_reduce()
{
    int head = blockIdx.x;
    int t = threadIdx.x;
    __half* kvt = g_kvt2 + (size_t)head * 64 * 256;
    for (int e = t; e < 128 * HD_; e += 256) {
        int d = e >> 6, m = e & 63;
        float s = 0.f;
        #pragma unroll
        for (int c = 0; c < NCHUNK; c++)
            s += g_kvp[((size_t)(c * BH_ + head)) * 128 * HD_ + e];
        __half hi = __float2half_rn(s);
        __half lo = __float2half_rn(s - __half2float(hi));
        kvt[m * 256 + d]       = hi;
        kvt[m * 256 + 128 + d] = lo;
    }
    if (t < 128) {
        float s = 0.f;
        #pragma unroll
        for (int c = 0; c < NCHUNK; c++)
            s += g_ksump[(c * BH_ + head) * 128 + t];
        g_ksum[head * 128 + t] = s;
    }
}

// ================= attn via HMMA =================
// Per block: 128 l-rows of one head. A = q_ split [qh|ql] (4 slabs of k64),
// B = kvt2 [kvh|kvl] (4 slabs). Passes (A,B): (0,0)(1,1)(2,0)(3,1)(0,2)(1,3)
// = (qh+ql).kvh + qh.kvl  (residual ql.kvl ~2^-22).
#define ATT_A_SM 65536            // 4 slabs * 128 rows * 128B
#define ATT_B_SM 32768            // 4 slabs * 64 rows * 128B
#define ATT_DSMEM (ATT_A_SM + ATT_B_SM + 128)

__global__ __launch_bounds__(256, 2)
void attn_hmma(const float* __restrict__ q)
{
    extern __shared__ char dsm[];
    __shared__ float ss[128], cs[128], zs[128], ks_s[128];

    const int t = threadIdx.x;
    const int wid = t >> 5, lane = t & 31;
    const int ltile = blockIdx.x;           // 0..31
    const int head  = blockIdx.y;           // 0..63
    const int b = head / H_, h = head % H_;

    char* sm = (char*)((((uintptr_t)dsm) + 127) & ~(uintptr_t)127);
    uint32_t sA = smem_u32(sm);
    uint32_t sB = sA + ATT_A_SM;

    // stage 0: per-row sincos + ksum to smem
    if (t < 128) {
        int l = ltile * 128 + t;
        float ang = (float)M_PI * 0.5f * (float)(l + 1) / (float)L_;
        sincosf(ang, &ss[t], &cs[t]);
        ks_s[t] = g_ksum[head * 128 + t];
    }

    // B tile loads (async)
    {
        const __half* kvt = g_kvt2 + (size_t)head * 64 * 256;
        #pragma unroll
        for (int j = 0; j < 8; j++) {
            int i = t + j * 256;            // 0..2047 16B chunks
            int row = i >> 5, c = i & 31;
            int slab = c >> 3, cc = c & 7;
            cp_async16(sB + slab * 8192 + swz(row * 128 + cc * 16),
                       kvt + row * 256 + c * 8);
        }
        cp_commit();
    }
    __syncthreads();   // ss/cs/ks_s ready

    // step A: build q_ fp16 split into sA slabs + z partials
    {
        const int l_loc = t >> 1;           // 0..127
        const int halfsel = t & 1;          // which 64 of the 128 d'
        int lg = ltile * 128 + l_loc;
        const float* qrow = q + ((size_t)(b * L_ + lg)) * E_ + h * HD_;
        float w = halfsel ? cs[l_loc] : ss[l_loc];
        float zpart = 0.f;
        char* aw_hi = sm + halfsel * 16384;
        char* aw_lo = sm + (2 + halfsel) * 16384;
        #pragma unroll 4
        for (int it = 0; it < 32; it++) {
            int dp = halfsel * 64 + 2 * it;         // even d'
            float q0 = qrow[dp & 63];
            float q1 = qrow[(dp & 63) + 1];
            float f0 = w * q0, f1 = w * q1;
            zpart += f0 * ks_s[dp] + f1 * ks_s[dp + 1];
            __half h0 = __float2half_rn(f0), h1 = __float2half_rn(f1);
            __half e0 = __float2half_rn(f0 - __half2float(h0));
            __half e1 = __float2half_rn(f1 - __half2float(h1));
            union { __half x[2]; uint32_t u; } H, Lw;
            H.x[0] = h0; H.x[1] = h1;
            Lw.x[0] = e0; Lw.x[1] = e1;
            uint32_t off = swz((uint32_t)l_loc * 128 + (dp & 63) * 2);
            *(uint32_t*)(aw_hi + off) = H.u;
            *(uint32_t*)(aw_lo + off) = Lw.u;
        }
        zpart += __shfl_xor_sync(0xffffffffu, zpart, 1);
        if (!halfsel) zs[l_loc] = 1.f / fmaxf(zpart, EPS_);
    }

    cp_wait_group<0>();
    __syncthreads();

    // MMA: warp tile 64 l x 16 n
    const int wm = wid & 1;                 // 0..1
    const int wn = wid >> 1;                // 0..3
    const int lrow = lane & 15;
    const int lhalf = (lane >> 4) * 16;

    float acc[4][2][4];
    #pragma unroll
    for (int mi = 0; mi < 4; mi++)
        #pragma unroll
        for (int hi = 0; hi < 2; hi++)
            #pragma unroll
            for (int r = 0; r < 4; r++) acc[mi][hi][r] = 0.f;

    const int As_idx[6] = {0, 1, 2, 3, 0, 1};
    const int Bs_idx[6] = {0, 1, 0, 1, 2, 3};
    #pragma unroll
    for (int p = 0; p < 6; p++) {
        uint32_t a_s = sA + As_idx[p] * 16384;
        uint32_t b_s = sB + Bs_idx[p] * 8192;
        #pragma unroll
        for (int kk = 0; kk < 4; kk++) {
            uint32_t a[4][4], bfr[4];
            #pragma unroll
            for (int mi = 0; mi < 4; mi++) {
                uint32_t off = (uint32_t)(wm * 64 + mi * 16 + lrow) * 128 + kk * 32 + lhalf;
                ldmatrix_x4(a[mi], a_s + swz(off));
            }
            {
                uint32_t off = (uint32_t)(wn * 16 + lrow) * 128 + kk * 32 + lhalf;
                ldmatrix_x4(bfr, b_s + swz(off));
            }
            #pragma unroll
            for (int mi = 0; mi < 4; mi++)
                #pragma unroll
                for (int hi = 0; hi < 2; hi++)
                    mma_fp16(acc[mi][hi], a[mi], bfr[hi], bfr[hi + 2]);
        }
    }

    // epilogue: z-scale + split fp16 write
    const int qr = lane >> 2;
    const int qc = (lane & 3) * 2;
    #pragma unroll
    for (int mi = 0; mi < 4; mi++) {
        #pragma unroll
        for (int hi = 0; hi < 2; hi++) {
            #pragma unroll
            for (int r = 0; r < 2; r++) {
                int lloc = wm * 64 + mi * 16 + qr + r * 8;
                int n = wn * 16 + hi * 8 + qc;
                float z = zs[lloc];
                float v0 = acc[mi][hi][r * 2 + 0] * z;
                float v1 = acc[mi][hi][r * 2 + 1] * z;
                __half h0 = __float2half_rn(v0), h1 = __float2half_rn(v1);
                __half e0 = __float2half_rn(v0 - __half2float(h0));
                __half e1 = __float2half_rn(v1 - __half2float(h1));
                union { __half x[2]; uint32_t u; } Hh, Ll;
                Hh.x[0] = h0; Hh.x[1] = h1;
                Ll.x[0] = e0; Ll.x[1] = e1;
                __half* ob = g_attn2 + ((size_t)(b * L_ + ltile * 128 + lloc)) * KTOT
                           + h * HD_ + n;
                *(uint32_t*)(ob)        = Hh.u;
                *(uint32_t*)(ob + 1024) = Ll.u;
            }
        }
    }
}

// ================= launcher =================
extern "C" void kernel_launch(void* const* d_in, const int* in_sizes, int n_in,
                              void* d_out, int out_size)
{
    const float* x  = (const float*)d_in[0];
    const float* Wq = (const float*)d_in[1];
    const float* bq = (const float*)d_in[2];
    const float* Wk = (const float*)d_in[3];
    const float* bk = (const float*)d_in[4];
    const float* Wv = (const float*)d_in[5];
    const float* bv = (const float*)d_in[6];
    const float* Wo = (const float*)d_in[7];
    const float* bo = (const float*)d_in[8];
    float* out = (float*)d_out;

    __half *x2, *attn2, *w2;
    float *q, *k, *v;
    cudaGetSymbolAddress((void**)&x2,    g_x2);
    cudaGetSymbolAddress((void**)&attn2, g_attn2);
    cudaGetSymbolAddress((void**)&w2,    g_w2);
    cudaGetSymbolAddress((void**)&q,     g_q);
    cudaGetSymbolAddress((void**)&k,     g_k);
    cudaGetSymbolAddress((void**)&v,     g_v);
    __half* w2q = w2;                                    // rows 0..1023
    __half* w2k = w2 + (size_t)1 * E_ * KTOT;            // rows 1024..2047
    __half* w2v = w2 + (size_t)2 * E_ * KTOT;            // rows 2048..3071
    __half* w2o = w2 + (size_t)3 * E_ * KTOT;

    cudaFuncSetAttribute(gemm_mma,  cudaFuncAttributeMaxDynamicSharedMemorySize, GEMM_DSMEM);
    cudaFuncSetAttribute(gemm_qkv,  cudaFuncAttributeMaxDynamicSharedMemorySize, GEMM_DSMEM);
    cudaFuncSetAttribute(attn_hmma, cudaFuncAttributeMaxDynamicSharedMemorySize, ATT_DSMEM);

    // split conversions
    split_kernel<1><<<M_ * (E_/4) / 256, 256>>>(x, x2, M_);
    split_kernel<0><<<E_ * (E_/4) / 256, 256>>>(Wq, w2q, E_);
    split_kernel<0><<<E_ * (E_/4) / 256, 256>>>(Wk, w2k, E_);
    split_kernel<0><<<E_ * (E_/4) / 256, 256>>>(Wv, w2v, E_);
    split_kernel<0><<<E_ * (E_/4) / 256, 256>>>(Wo, w2o, E_);

    // merged QKV projection
    gemm_qkv<<<dim3(3 * E_ / GBN, M_ / GBM), 256, GEMM_DSMEM>>>(
        x2, w2, bq, bk, bv, q, k, v);

    kv_partial<<<dim3(BH_, NCHUNK), 256>>>(k, v);
    kv_reduce<<<BH_, 256>>>();
    attn_hmma<<<dim3(32, BH_), 256, ATT_DSMEM>>>(q);

    gemm_mma<<<dim3(E_ / GBN, M_ / GBM), 256, GEMM_DSMEM>>>(attn2, w2o, bo, out);
}

// round 8
// speedup vs baseline: 2.4743x; 1.5198x over previous
#include <cuda_runtime.h>
#include <cuda_fp16.h>
#include <math.h>
#include <stdint.h>

#define B_   4
#define L_   4096
#define E_   1024
#define H_   16
#define HD_  64
#define M_   (B_*L_)    // 16384 rows
#define BH_  (B_*H_)    // 64 heads
#define EPS_ 1e-4f
#define KTOT 1024       // plain 1-term fp16
#define NCHUNK 8        // kv l-chunks

// ---------------- scratch (no allocations allowed) ----------------
__device__ __half g_x2[(size_t)M_*KTOT];
__device__ __half g_attn2[(size_t)M_*KTOT];
__device__ __half g_w2[4][(size_t)E_*KTOT];
__device__ float g_q[(size_t)M_*E_];
__device__ float g_k[(size_t)M_*E_];
__device__ float g_v[(size_t)M_*E_];
__device__ float g_kvp[NCHUNK*BH_*128*HD_];
__device__ float g_ksump[NCHUNK*BH_*128];
__device__ float g_ksum[BH_*128];
__device__ __half g_kvt2[(size_t)BH_*64*256];  // per head: [64 m][kvh(128) | kvl(128)]

// ================= PTX helpers (sm_80-generic only!) =================
__device__ __forceinline__ uint32_t smem_u32(const void* p) {
    uint32_t a;
    asm("{ .reg .u64 t; cvta.to.shared.u64 t, %1; cvt.u32.u64 %0, t; }" : "=r"(a) : "l"(p));
    return a;
}
__device__ __forceinline__ void cp_async16(uint32_t saddr, const void* gaddr) {
    asm volatile("cp.async.cg.shared.global [%0], [%1], 16;" :: "r"(saddr), "l"(gaddr) : "memory");
}
__device__ __forceinline__ void cp_commit() {
    asm volatile("cp.async.commit_group;" ::: "memory");
}
template<int N> __device__ __forceinline__ void cp_wait_group() {
    asm volatile("cp.async.wait_group %0;" :: "n"(N) : "memory");
}
__device__ __forceinline__ void ldmatrix_x4(uint32_t* r, uint32_t addr) {
    asm volatile("ldmatrix.sync.aligned.m8n8.x4.shared.b16 {%0,%1,%2,%3}, [%4];"
        : "=r"(r[0]), "=r"(r[1]), "=r"(r[2]), "=r"(r[3]) : "r"(addr));
}
__device__ __forceinline__ void mma_fp16(float* c, const uint32_t* a, uint32_t b0, uint32_t b1) {
    asm volatile("mma.sync.aligned.m16n8k16.row.col.f32.f16.f16.f32 "
        "{%0,%1,%2,%3}, {%4,%5,%6,%7}, {%8,%9}, {%0,%1,%2,%3};"
        : "+f"(c[0]), "+f"(c[1]), "+f"(c[2]), "+f"(c[3])
        : "r"(a[0]), "r"(a[1]), "r"(a[2]), "r"(a[3]), "r"(b0), "r"(b1));
}
__device__ __forceinline__ uint32_t swz(uint32_t off) { return off ^ ((off >> 3) & 0x70); }

// ================= fp32 -> fp16 convert =================
__global__ void convert_kernel(const float* __restrict__ in, __half* __restrict__ out, int rows)
{
    int idx = blockIdx.x * blockDim.x + threadIdx.x;          // one float4 per thread
    int total = rows * (E_ / 4);
    if (idx >= total) return;
    float4 v = *(const float4*)&in[(size_t)idx * 4];
    union { __half b[4]; uint2 u; } Hh;
    Hh.b[0] = __float2half_rn(v.x);
    Hh.b[1] = __float2half_rn(v.y);
    Hh.b[2] = __float2half_rn(v.z);
    Hh.b[3] = __float2half_rn(v.w);
    *(uint2*)&out[(size_t)idx * 4] = Hh.u;
}

// ================= HMMA GEMM =================
// Tile 128x128x64, 8 warps, warp tile 64x32, mma.sync m16n8k16.
#define GBM 128
#define GBN 128
#define SLAB 64                 // fp16 K per slab = 128 bytes per row
#define NSLAB (KTOT/SLAB)       // 16
#define NSTG 3
#define AB_BYTES (GBM*128)      // 16384 (A tile == B tile size)
#define STG_BYTES (2*AB_BYTES)  // 32768
#define GEMM_DSMEM (NSTG*STG_BYTES + 1024)

__device__ __forceinline__ void gemm_issue_loads(
    const __half* ga, const __half* gw,
    uint32_t base, int slab, int buf, int t)
{
    int k0 = slab * SLAB;
    uint32_t stA = base + buf * STG_BYTES;
    uint32_t stW = stA + AB_BYTES;
    const __half* gak = ga + k0;
    const __half* gwk = gw + k0;
    #pragma unroll
    for (int j = 0; j < 4; j++) {
        int i = t + j * 256;            // 0..1023
        int row = i >> 3, c = i & 7;
        cp_async16(stA + swz(row * 128 + c * 16), gak + (size_t)row * KTOT + c * 8);
    }
    #pragma unroll
    for (int j = 0; j < 4; j++) {
        int i = t + j * 256;
        int row = i >> 3, c = i & 7;
        cp_async16(stW + swz(row * 128 + c * 16), gwk + (size_t)row * KTOT + c * 8);
    }
    cp_commit();
}

struct GemmFrag { float acc[4][4][4]; };

__device__ __forceinline__ void gemm_mainloop(
    const __half* ga, const __half* gw, uint32_t base, int t, GemmFrag& F)
{
    const int wid = t >> 5, lane = t & 31;
    const int wm = wid >> 2;
    const int wn = wid & 3;
    #pragma unroll
    for (int mi = 0; mi < 4; mi++)
        #pragma unroll
        for (int ni = 0; ni < 4; ni++)
            #pragma unroll
            for (int r = 0; r < 4; r++) F.acc[mi][ni][r] = 0.f;

    #pragma unroll
    for (int s = 0; s < NSTG - 1; s++) gemm_issue_loads(ga, gw, base, s, s, t);

    const int lrow = lane & 15;
    const int lhalf = (lane >> 4) * 16;

    for (int i = 0; i < NSLAB; i++) {
        cp_wait_group<NSTG - 2>();
        __syncthreads();
        if (i + NSTG - 1 < NSLAB)
            gemm_issue_loads(ga, gw, base, i + NSTG - 1, (i + NSTG - 1) % NSTG, t);
        else
            cp_commit();

        uint32_t sA = base + (i % NSTG) * STG_BYTES;
        uint32_t sB = sA + AB_BYTES;

        #pragma unroll
        for (int kk = 0; kk < 4; kk++) {
            uint32_t a[4][4], b[2][4];
            #pragma unroll
            for (int mi = 0; mi < 4; mi++) {
                uint32_t off = (uint32_t)(wm * 64 + mi * 16 + lrow) * 128 + kk * 32 + lhalf;
                ldmatrix_x4(a[mi], sA + swz(off));
            }
            #pragma unroll
            for (int nb = 0; nb < 2; nb++) {
                uint32_t off = (uint32_t)(wn * 32 + nb * 16 + lrow) * 128 + kk * 32 + lhalf;
                ldmatrix_x4(b[nb], sB + swz(off));
            }
            #pragma unroll
            for (int mi = 0; mi < 4; mi++)
                #pragma unroll
                for (int ni = 0; ni < 4; ni++) {
                    int nb = ni >> 1, hi = ni & 1;
                    mma_fp16(F.acc[mi][ni], a[mi], b[nb][hi], b[nb][hi + 2]);
                }
        }
        __syncthreads();
    }
}

__device__ __forceinline__ void gemm_epilogue(
    GemmFrag& F, const float* bias, float* C, int bm, int cn, bool relu, int t)
{
    const int wid = t >> 5, lane = t & 31;
    const int wm = wid >> 2, wn = wid & 3;
    const int qrow = lane >> 2;
    const int qcol = (lane & 3) * 2;
    #pragma unroll
    for (int mi = 0; mi < 4; mi++) {
        int row0 = bm + wm * 64 + mi * 16 + qrow;
        #pragma unroll
        for (int ni = 0; ni < 4; ni++) {
            int col = cn + wn * 32 + ni * 8 + qcol;
            float2 bb = *(const float2*)&bias[col];
            float v0 = F.acc[mi][ni][0] + bb.x;
            float v1 = F.acc[mi][ni][1] + bb.y;
            float v2 = F.acc[mi][ni][2] + bb.x;
            float v3 = F.acc[mi][ni][3] + bb.y;
            if (relu) {
                v0 = fmaxf(v0, 0.f); v1 = fmaxf(v1, 0.f);
                v2 = fmaxf(v2, 0.f); v3 = fmaxf(v3, 0.f);
            }
            *(float2*)&C[(size_t)row0 * E_ + col]       = make_float2(v0, v1);
            *(float2*)&C[(size_t)(row0 + 8) * E_ + col] = make_float2(v2, v3);
        }
    }
}

// Merged Q/K/V projection: W2all = [Wq2; Wk2; Wv2] rows 0..3071
__global__ __launch_bounds__(256, 2)
void gemm_qkv(const __half* __restrict__ A2, const __half* __restrict__ W2all,
              const float* __restrict__ bq, const float* __restrict__ bk,
              const float* __restrict__ bv,
              float* __restrict__ qp, float* __restrict__ kp, float* __restrict__ vp)
{
    extern __shared__ char dsm[];
    const int t = threadIdx.x;
    const int bm = blockIdx.y * GBM;
    const int bnG = blockIdx.x * GBN;          // 0..2944
    const int seg = bnG >> 10;                 // 0=q 1=k 2=v
    const int cn = bnG & 1023;

    uint32_t base = (smem_u32(dsm) + 1023u) & ~1023u;
    const __half* ga = A2 + (size_t)bm * KTOT;
    const __half* gw = W2all + (size_t)bnG * KTOT;

    GemmFrag F;
    gemm_mainloop(ga, gw, base, t, F);

    const float* bias = (seg == 0) ? bq : (seg == 1) ? bk : bv;
    float* C = (seg == 0) ? qp : (seg == 1) ? kp : vp;
    gemm_epilogue(F, bias, C, bm, cn, seg < 2, t);
}

// Single-output GEMM (used for Wo)
__global__ __launch_bounds__(256, 2)
void gemm_mma(const __half* __restrict__ A2, const __half* __restrict__ W2,
              const float* __restrict__ bias, float* __restrict__ C)
{
    extern __shared__ char dsm[];
    const int t = threadIdx.x;
    const int bm = blockIdx.y * GBM;
    const int bn = blockIdx.x * GBN;

    uint32_t base = (smem_u32(dsm) + 1023u) & ~1023u;
    const __half* ga = A2 + (size_t)bm * KTOT;
    const __half* gw = W2 + (size_t)bn * KTOT;

    GemmFrag F;
    gemm_mainloop(ga, gw, base, t, F);
    gemm_epilogue(F, bias, C, bm, bn, false, t);
}

// ================= kv partial + reduce =================
__global__ __launch_bounds__(256)
void kv_partial(const float* __restrict__ k, const float* __restrict__ v)
{
    const int head = blockIdx.x;            // 0..63
    const int chunk = blockIdx.y;           // 0..7
    const int b = head / H_, h = head % H_;
    __shared__ float ks[32][128];
    __shared__ float vs[32][68];

    const int t  = threadIdx.x;
    const int tx = t & 15;
    const int ty = t >> 4;

    float acc[8][4];
    #pragma unroll
    for (int i = 0; i < 8; i++)
        #pragma unroll
        for (int j = 0; j < 4; j++) acc[i][j] = 0.f;
    float ksum_acc = 0.f;

    const int l_begin = chunk * (L_ / NCHUNK);
    const int l_end   = l_begin + (L_ / NCHUNK);

    for (int l0 = l_begin; l0 < l_end; l0 += 32) {
        #pragma unroll
        for (int r = 0; r < 2; r++) {
            int i   = t + r * 256;
            int row = i >> 4;
            int c4  = (i & 15) * 4;
            int l   = l0 + row;
            float ang = (float)M_PI * 0.5f * (float)(l + 1) / (float)L_;
            float s, c;
            sincosf(ang, &s, &c);
            size_t bse = ((size_t)(b * L_ + l)) * E_ + h * HD_ + c4;
            float4 kk4 = *(const float4*)&k[bse];
            ks[row][c4+0]    = s * kk4.x; ks[row][c4+1]    = s * kk4.y;
            ks[row][c4+2]    = s * kk4.z; ks[row][c4+3]    = s * kk4.w;
            ks[row][64+c4+0] = c * kk4.x; ks[row][64+c4+1] = c * kk4.y;
            ks[row][64+c4+2] = c * kk4.z; ks[row][64+c4+3] = c * kk4.w;
            float4 vv4 = *(const float4*)&v[bse];
            vs[row][c4+0] = vv4.x; vs[row][c4+1] = vv4.y;
            vs[row][c4+2] = vv4.z; vs[row][c4+3] = vv4.w;
        }
        __syncthreads();

        if (t < 128) {
            #pragma unroll
            for (int l = 0; l < 32; l++) ksum_acc += ks[l][t];
        }
        #pragma unroll 4
        for (int l = 0; l < 32; l++) {
            float a[8], bb[4];
            #pragma unroll
            for (int i = 0; i < 8; i++) a[i]  = ks[l][ty*8 + i];
            #pragma unroll
            for (int j = 0; j < 4; j++) bb[j] = vs[l][tx*4 + j];
            #pragma unroll
            for (int i = 0; i < 8; i++)
                #pragma unroll
                for (int j = 0; j < 4; j++)
                    acc[i][j] += a[i] * bb[j];
        }
        __syncthreads();
    }

    float* kvout = &g_kvp[((size_t)(chunk * BH_ + head)) * 128 * HD_];
    #pragma unroll
    for (int i = 0; i < 8; i++)
        #pragma unroll
        for (int j = 0; j < 4; j++)
            kvout[(ty*8 + i) * HD_ + tx*4 + j] = acc[i][j];
    if (t < 128) g_ksump[(chunk * BH_ + head) * 128 + t] = ksum_acc;
}

// Reduce partials; emit transposed fp16 2-term kv: g_kvt2[head][m][ kvh(d) | kvl(d) ]
__global__ __launch_bounds__(256)
void kv_reduce()
{
    int head = blockIdx.x;
    int t = threadIdx.x;
    __half* kvt = g_kvt2 + (size_t)head * 64 * 256;
    for (int e = t; e < 128 * HD_; e += 256) {
        int d = e >> 6, m = e & 63;
        float s = 0.f;
        #pragma unroll
        for (int c = 0; c < NCHUNK; c++)
            s += g_kvp[((size_t)(c * BH_ + head)) * 128 * HD_ + e];
        __half hi = __float2half_rn(s);
        __half lo = __float2half_rn(s - __half2float(hi));
        kvt[m * 256 + d]       = hi;
        kvt[m * 256 + 128 + d] = lo;
    }
    if (t < 128) {
        float s = 0.f;
        #pragma unroll
        for (int c = 0; c < NCHUNK; c++)
            s += g_ksump[(c * BH_ + head) * 128 + t];
        g_ksum[head * 128 + t] = s;
    }
}

// ================= attn via HMMA =================
// Per block: 128 l-rows of one head. A = q_ split [qh|ql] (4 slabs of k64),
// B = kvt2 [kvh|kvl] (4 slabs). Passes: (qh+ql).kvh + qh.kvl.
#define ATT_A_SM 65536            // 4 slabs * 128 rows * 128B
#define ATT_B_SM 32768            // 4 slabs * 64 rows * 128B
#define ATT_DSMEM (ATT_A_SM + ATT_B_SM + 128)

__global__ __launch_bounds__(256, 2)
void attn_hmma(const float* __restrict__ q)
{
    extern __shared__ char dsm[];
    __shared__ float ss[128], cs[128], zs[128], ks_s[128];

    const int t = threadIdx.x;
    const int wid = t >> 5, lane = t & 31;
    const int ltile = blockIdx.x;           // 0..31
    const int head  = blockIdx.y;           // 0..63
    const int b = head / H_, h = head % H_;

    char* sm = (char*)((((uintptr_t)dsm) + 127) & ~(uintptr_t)127);
    uint32_t sA = smem_u32(sm);
    uint32_t sB = sA + ATT_A_SM;

    if (t < 128) {
        int l = ltile * 128 + t;
        float ang = (float)M_PI * 0.5f * (float)(l + 1) / (float)L_;
        sincosf(ang, &ss[t], &cs[t]);
        ks_s[t] = g_ksum[head * 128 + t];
    }

    {
        const __half* kvt = g_kvt2 + (size_t)head * 64 * 256;
        #pragma unroll
        for (int j = 0; j < 8; j++) {
            int i = t + j * 256;            // 0..2047 16B chunks
            int row = i >> 5, c = i & 31;
            int slab = c >> 3, cc = c & 7;
            cp_async16(sB + slab * 8192 + swz(row * 128 + cc * 16),
                       kvt + row * 256 + c * 8);
        }
        cp_commit();
    }
    __syncthreads();

    {
        const int l_loc = t >> 1;           // 0..127
        const int halfsel = t & 1;
        int lg = ltile * 128 + l_loc;
        const float* qrow = q + ((size_t)(b * L_ + lg)) * E_ + h * HD_;
        float w = halfsel ? cs[l_loc] : ss[l_loc];
        float zpart = 0.f;
        char* aw_hi = sm + halfsel * 16384;
        char* aw_lo = sm + (2 + halfsel) * 16384;
        #pragma unroll 4
        for (int it = 0; it < 32; it++) {
            int dp = halfsel * 64 + 2 * it;
            float q0 = qrow[dp & 63];
            float q1 = qrow[(dp & 63) + 1];
            float f0 = w * q0, f1 = w * q1;
            zpart += f0 * ks_s[dp] + f1 * ks_s[dp + 1];
            __half h0 = __float2half_rn(f0), h1 = __float2half_rn(f1);
            __half e0 = __float2half_rn(f0 - __half2float(h0));
            __half e1 = __float2half_rn(f1 - __half2float(h1));
            union { __half x[2]; uint32_t u; } H, Lw;
            H.x[0] = h0; H.x[1] = h1;
            Lw.x[0] = e0; Lw.x[1] = e1;
            uint32_t off = swz((uint32_t)l_loc * 128 + (dp & 63) * 2);
            *(uint32_t*)(aw_hi + off) = H.u;
            *(uint32_t*)(aw_lo + off) = Lw.u;
        }
        zpart += __shfl_xor_sync(0xffffffffu, zpart, 1);
        if (!halfsel) zs[l_loc] = 1.f / fmaxf(zpart, EPS_);
    }

    cp_wait_group<0>();
    __syncthreads();

    const int wm = wid & 1;
    const int wn = wid >> 1;
    const int lrow = lane & 15;
    const int lhalf = (lane >> 4) * 16;

    float acc[4][2][4];
    #pragma unroll
    for (int mi = 0; mi < 4; mi++)
        #pragma unroll
        for (int hi = 0; hi < 2; hi++)
            #pragma unroll
            for (int r = 0; r < 4; r++) acc[mi][hi][r] = 0.f;

    const int As_idx[6] = {0, 1, 2, 3, 0, 1};
    const int Bs_idx[6] = {0, 1, 0, 1, 2, 3};
    #pragma unroll
    for (int p = 0; p < 6; p++) {
        uint32_t a_s = sA + As_idx[p] * 16384;
        uint32_t b_s = sB + Bs_idx[p] * 8192;
        #pragma unroll
        for (int kk = 0; kk < 4; kk++) {
            uint32_t a[4][4], bfr[4];
            #pragma unroll
            for (int mi = 0; mi < 4; mi++) {
                uint32_t off = (uint32_t)(wm * 64 + mi * 16 + lrow) * 128 + kk * 32 + lhalf;
                ldmatrix_x4(a[mi], a_s + swz(off));
            }
            {
                uint32_t off = (uint32_t)(wn * 16 + lrow) * 128 + kk * 32 + lhalf;
                ldmatrix_x4(bfr, b_s + swz(off));
            }
            #pragma unroll
            for (int mi = 0; mi < 4; mi++)
                #pragma unroll
                for (int hi = 0; hi < 2; hi++)
                    mma_fp16(acc[mi][hi], a[mi], bfr[hi], bfr[hi + 2]);
        }
    }

    // epilogue: z-scale + single fp16 write
    const int qr = lane >> 2;
    const int qc = (lane & 3) * 2;
    #pragma unroll
    for (int mi = 0; mi < 4; mi++) {
        #pragma unroll
        for (int hi = 0; hi < 2; hi++) {
            #pragma unroll
            for (int r = 0; r < 2; r++) {
                int lloc = wm * 64 + mi * 16 + qr + r * 8;
                int n = wn * 16 + hi * 8 + qc;
                float z = zs[lloc];
                float v0 = acc[mi][hi][r * 2 + 0] * z;
                float v1 = acc[mi][hi][r * 2 + 1] * z;
                union { __half x[2]; uint32_t u; } Hh;
                Hh.x[0] = __float2half_rn(v0);
                Hh.x[1] = __float2half_rn(v1);
                __half* ob = g_attn2 + ((size_t)(b * L_ + ltile * 128 + lloc)) * KTOT
                           + h * HD_ + n;
                *(uint32_t*)(ob) = Hh.u;
            }
        }
    }
}

// ================= launcher =================
extern "C" void kernel_launch(void* const* d_in, const int* in_sizes, int n_in,
                              void* d_out, int out_size)
{
    const float* x  = (const float*)d_in[0];
    const float* Wq = (const float*)d_in[1];
    const float* bq = (const float*)d_in[2];
    const float* Wk = (const float*)d_in[3];
    const float* bk = (const float*)d_in[4];
    const float* Wv = (const float*)d_in[5];
    const float* bv = (const float*)d_in[6];
    const float* Wo = (const float*)d_in[7];
    const float* bo = (const float*)d_in[8];
    float* out = (float*)d_out;

    __half *x2, *attn2, *w2;
    float *q, *k, *v;
    cudaGetSymbolAddress((void**)&x2,    g_x2);
    cudaGetSymbolAddress((void**)&attn2, g_attn2);
    cudaGetSymbolAddress((void**)&w2,    g_w2);
    cudaGetSymbolAddress((void**)&q,     g_q);
    cudaGetSymbolAddress((void**)&k,     g_k);
    cudaGetSymbolAddress((void**)&v,     g_v);
    __half* w2q = w2;                                    // rows 0..1023
    __half* w2k = w2 + (size_t)1 * E_ * KTOT;            // rows 1024..2047
    __half* w2v = w2 + (size_t)2 * E_ * KTOT;            // rows 2048..3071
    __half* w2o = w2 + (size_t)3 * E_ * KTOT;

    cudaFuncSetAttribute(gemm_mma,  cudaFuncAttributeMaxDynamicSharedMemorySize, GEMM_DSMEM);
    cudaFuncSetAttribute(gemm_qkv,  cudaFuncAttributeMaxDynamicSharedMemorySize, GEMM_DSMEM);
    cudaFuncSetAttribute(attn_hmma, cudaFuncAttributeMaxDynamicSharedMemorySize, ATT_DSMEM);

    // fp16 conversions
    convert_kernel<<<M_ * (E_/4) / 256, 256>>>(x, x2, M_);
    convert_kernel<<<E_ * (E_/4) / 256, 256>>>(Wq, w2q, E_);
    convert_kernel<<<E_ * (E_/4) / 256, 256>>>(Wk, w2k, E_);
    convert_kernel<<<E_ * (E_/4) / 256, 256>>>(Wv, w2v, E_);
    convert_kernel<<<E_ * (E_/4) / 256, 256>>>(Wo, w2o, E_);

    // merged QKV projection
    gemm_qkv<<<dim3(3 * E_ / GBN, M_ / GBM), 256, GEMM_DSMEM>>>(
        x2, w2, bq, bk, bv, q, k, v);

    kv_partial<<<dim3(BH_, NCHUNK), 256>>>(k, v);
    kv_reduce<<<BH_, 256>>>();
    attn_hmma<<<dim3(32, BH_), 256, ATT_DSMEM>>>(q);

    gemm_mma<<<dim3(E_ / GBN, M_ / GBM), 256, GEMM_DSMEM>>>(attn2, w2o, bo, out);
}

// round 9
// speedup vs baseline: 2.7286x; 1.1028x over previous
#include <cuda_runtime.h>
#include <cuda_fp16.h>
#include <math.h>
#include <stdint.h>

#define B_   4
#define L_   4096
#define E_   1024
#define H_   16
#define HD_  64
#define M_   (B_*L_)    // 16384 rows
#define BH_  (B_*H_)    // 64 heads
#define EPS_ 1e-4f
#define KTOT 1024       // plain 1-term fp16
#define NCHUNK 8        // kv l-chunks
#define KVCH (L_/NCHUNK) // 512

// ---------------- scratch (no allocations allowed) ----------------
__device__ __half g_x2[(size_t)M_*KTOT];
__device__ __half g_attn2[(size_t)M_*KTOT];
__device__ __half g_w2[4][(size_t)E_*KTOT];
__device__ float g_q[(size_t)M_*E_];
__device__ float g_k[(size_t)M_*E_];
__device__ float g_v[(size_t)M_*E_];
__device__ float g_kvp[NCHUNK*BH_*128*HD_];
__device__ float g_ksump[NCHUNK*BH_*128];
__device__ float g_ksum[BH_*128];
__device__ __half g_kvt2[(size_t)BH_*64*256];  // per head: [64 m][kvh(128) | kvl(128)]

// ================= PTX helpers (sm_80-generic only!) =================
__device__ __forceinline__ uint32_t smem_u32(const void* p) {
    uint32_t a;
    asm("{ .reg .u64 t; cvta.to.shared.u64 t, %1; cvt.u32.u64 %0, t; }" : "=r"(a) : "l"(p));
    return a;
}
__device__ __forceinline__ void cp_async16(uint32_t saddr, const void* gaddr) {
    asm volatile("cp.async.cg.shared.global [%0], [%1], 16;" :: "r"(saddr), "l"(gaddr) : "memory");
}
__device__ __forceinline__ void cp_commit() {
    asm volatile("cp.async.commit_group;" ::: "memory");
}
template<int N> __device__ __forceinline__ void cp_wait_group() {
    asm volatile("cp.async.wait_group %0;" :: "n"(N) : "memory");
}
__device__ __forceinline__ void ldmatrix_x4(uint32_t* r, uint32_t addr) {
    asm volatile("ldmatrix.sync.aligned.m8n8.x4.shared.b16 {%0,%1,%2,%3}, [%4];"
        : "=r"(r[0]), "=r"(r[1]), "=r"(r[2]), "=r"(r[3]) : "r"(addr));
}
__device__ __forceinline__ void mma_fp16(float* c, const uint32_t* a, uint32_t b0, uint32_t b1) {
    asm volatile("mma.sync.aligned.m16n8k16.row.col.f32.f16.f16.f32 "
        "{%0,%1,%2,%3}, {%4,%5,%6,%7}, {%8,%9}, {%0,%1,%2,%3};"
        : "+f"(c[0]), "+f"(c[1]), "+f"(c[2]), "+f"(c[3])
        : "r"(a[0]), "r"(a[1]), "r"(a[2]), "r"(a[3]), "r"(b0), "r"(b1));
}
__device__ __forceinline__ uint32_t swz(uint32_t off) { return off ^ ((off >> 3) & 0x70); }

// ================= fp32 -> fp16 convert =================
__global__ void convert_kernel(const float* __restrict__ in, __half* __restrict__ out, int rows)
{
    int idx = blockIdx.x * blockDim.x + threadIdx.x;          // one float4 per thread
    int total = rows * (E_ / 4);
    if (idx >= total) return;
    float4 v = *(const float4*)&in[(size_t)idx * 4];
    union { __half b[4]; uint2 u; } Hh;
    Hh.b[0] = __float2half_rn(v.x);
    Hh.b[1] = __float2half_rn(v.y);
    Hh.b[2] = __float2half_rn(v.z);
    Hh.b[3] = __float2half_rn(v.w);
    *(uint2*)&out[(size_t)idx * 4] = Hh.u;
}

// convert 4 weight matrices in one launch (blockIdx.y selects source)
__global__ void convert_w_kernel(const float* __restrict__ w0, const float* __restrict__ w1,
                                 const float* __restrict__ w2s, const float* __restrict__ w3,
                                 __half* __restrict__ out)
{
    int seg = blockIdx.y;
    const float* in = (seg == 0) ? w0 : (seg == 1) ? w1 : (seg == 2) ? w2s : w3;
    int idx = blockIdx.x * blockDim.x + threadIdx.x;
    int total = E_ * (E_ / 4);
    if (idx >= total) return;
    float4 v = *(const float4*)&in[(size_t)idx * 4];
    union { __half b[4]; uint2 u; } Hh;
    Hh.b[0] = __float2half_rn(v.x);
    Hh.b[1] = __float2half_rn(v.y);
    Hh.b[2] = __float2half_rn(v.z);
    Hh.b[3] = __float2half_rn(v.w);
    *(uint2*)&out[(size_t)seg * E_ * KTOT + (size_t)idx * 4] = Hh.u;
}

// ================= HMMA GEMM =================
// Tile 128x128x64, 8 warps, warp tile 64x32, mma.sync m16n8k16.
#define GBM 128
#define GBN 128
#define SLAB 64                 // fp16 K per slab = 128 bytes per row
#define NSLAB (KTOT/SLAB)       // 16
#define NSTG 3
#define AB_BYTES (GBM*128)      // 16384 (A tile == B tile size)
#define STG_BYTES (2*AB_BYTES)  // 32768
#define GEMM_DSMEM (NSTG*STG_BYTES + 1024)

__device__ __forceinline__ void gemm_issue_loads(
    const __half* ga, const __half* gw,
    uint32_t base, int slab, int buf, int t)
{
    int k0 = slab * SLAB;
    uint32_t stA = base + buf * STG_BYTES;
    uint32_t stW = stA + AB_BYTES;
    const __half* gak = ga + k0;
    const __half* gwk = gw + k0;
    #pragma unroll
    for (int j = 0; j < 4; j++) {
        int i = t + j * 256;            // 0..1023
        int row = i >> 3, c = i & 7;
        cp_async16(stA + swz(row * 128 + c * 16), gak + (size_t)row * KTOT + c * 8);
    }
    #pragma unroll
    for (int j = 0; j < 4; j++) {
        int i = t + j * 256;
        int row = i >> 3, c = i & 7;
        cp_async16(stW + swz(row * 128 + c * 16), gwk + (size_t)row * KTOT + c * 8);
    }
    cp_commit();
}

struct GemmFrag { float acc[4][4][4]; };

__device__ __forceinline__ void gemm_mainloop(
    const __half* ga, const __half* gw, uint32_t base, int t, GemmFrag& F)
{
    const int wid = t >> 5, lane = t & 31;
    const int wm = wid >> 2;
    const int wn = wid & 3;
    #pragma unroll
    for (int mi = 0; mi < 4; mi++)
        #pragma unroll
        for (int ni = 0; ni < 4; ni++)
            #pragma unroll
            for (int r = 0; r < 4; r++) F.acc[mi][ni][r] = 0.f;

    #pragma unroll
    for (int s = 0; s < NSTG - 1; s++) gemm_issue_loads(ga, gw, base, s, s, t);

    const int lrow = lane & 15;
    const int lhalf = (lane >> 4) * 16;

    for (int i = 0; i < NSLAB; i++) {
        cp_wait_group<NSTG - 2>();
        __syncthreads();
        if (i + NSTG - 1 < NSLAB)
            gemm_issue_loads(ga, gw, base, i + NSTG - 1, (i + NSTG - 1) % NSTG, t);
        else
            cp_commit();

        uint32_t sA = base + (i % NSTG) * STG_BYTES;
        uint32_t sB = sA + AB_BYTES;

        #pragma unroll
        for (int kk = 0; kk < 4; kk++) {
            uint32_t a[4][4], b[2][4];
            #pragma unroll
            for (int mi = 0; mi < 4; mi++) {
                uint32_t off = (uint32_t)(wm * 64 + mi * 16 + lrow) * 128 + kk * 32 + lhalf;
                ldmatrix_x4(a[mi], sA + swz(off));
            }
            #pragma unroll
            for (int nb = 0; nb < 2; nb++) {
                uint32_t off = (uint32_t)(wn * 32 + nb * 16 + lrow) * 128 + kk * 32 + lhalf;
                ldmatrix_x4(b[nb], sB + swz(off));
            }
            #pragma unroll
            for (int mi = 0; mi < 4; mi++)
                #pragma unroll
                for (int ni = 0; ni < 4; ni++) {
                    int nb = ni >> 1, hi = ni & 1;
                    mma_fp16(F.acc[mi][ni], a[mi], b[nb][hi], b[nb][hi + 2]);
                }
        }
        __syncthreads();
    }
}

__device__ __forceinline__ void gemm_epilogue(
    GemmFrag& F, const float* bias, float* C, int bm, int cn, bool relu, int t)
{
    const int wid = t >> 5, lane = t & 31;
    const int wm = wid >> 2, wn = wid & 3;
    const int qrow = lane >> 2;
    const int qcol = (lane & 3) * 2;
    #pragma unroll
    for (int mi = 0; mi < 4; mi++) {
        int row0 = bm + wm * 64 + mi * 16 + qrow;
        #pragma unroll
        for (int ni = 0; ni < 4; ni++) {
            int col = cn + wn * 32 + ni * 8 + qcol;
            float2 bb = *(const float2*)&bias[col];
            float v0 = F.acc[mi][ni][0] + bb.x;
            float v1 = F.acc[mi][ni][1] + bb.y;
            float v2 = F.acc[mi][ni][2] + bb.x;
            float v3 = F.acc[mi][ni][3] + bb.y;
            if (relu) {
                v0 = fmaxf(v0, 0.f); v1 = fmaxf(v1, 0.f);
                v2 = fmaxf(v2, 0.f); v3 = fmaxf(v3, 0.f);
            }
            *(float2*)&C[(size_t)row0 * E_ + col]       = make_float2(v0, v1);
            *(float2*)&C[(size_t)(row0 + 8) * E_ + col] = make_float2(v2, v3);
        }
    }
}

// Merged Q/K/V projection: W2all = [Wq2; Wk2; Wv2] rows 0..3071
__global__ __launch_bounds__(256, 2)
void gemm_qkv(const __half* __restrict__ A2, const __half* __restrict__ W2all,
              const float* __restrict__ bq, const float* __restrict__ bk,
              const float* __restrict__ bv,
              float* __restrict__ qp, float* __restrict__ kp, float* __restrict__ vp)
{
    extern __shared__ char dsm[];
    const int t = threadIdx.x;
    const int bm = blockIdx.y * GBM;
    const int bnG = blockIdx.x * GBN;          // 0..2944
    const int seg = bnG >> 10;                 // 0=q 1=k 2=v
    const int cn = bnG & 1023;

    uint32_t base = (smem_u32(dsm) + 1023u) & ~1023u;
    const __half* ga = A2 + (size_t)bm * KTOT;
    const __half* gw = W2all + (size_t)bnG * KTOT;

    GemmFrag F;
    gemm_mainloop(ga, gw, base, t, F);

    const float* bias = (seg == 0) ? bq : (seg == 1) ? bk : bv;
    float* C = (seg == 0) ? qp : (seg == 1) ? kp : vp;
    gemm_epilogue(F, bias, C, bm, cn, seg < 2, t);
}

// Single-output GEMM (used for Wo)
__global__ __launch_bounds__(256, 2)
void gemm_mma(const __half* __restrict__ A2, const __half* __restrict__ W2,
              const float* __restrict__ bias, float* __restrict__ C)
{
    extern __shared__ char dsm[];
    const int t = threadIdx.x;
    const int bm = blockIdx.y * GBM;
    const int bn = blockIdx.x * GBN;

    uint32_t base = (smem_u32(dsm) + 1023u) & ~1023u;
    const __half* ga = A2 + (size_t)bm * KTOT;
    const __half* gw = W2 + (size_t)bn * KTOT;

    GemmFrag F;
    gemm_mainloop(ga, gw, base, t, F);
    gemm_epilogue(F, bias, C, bm, bn, false, t);
}

// ================= kv via HMMA =================
// Per block (head, chunk of 512 l): C[128 d'][72] = sum_l A[d'][l]*B[m][l]
// A[d'][l] = w(l,d')*k[l, d'%64] fp16 (transposed staging), B[m][l] = v[l][m] fp16.
// B row 64 = ones -> C[.,64] = ksum partial. Rows 65..79 zero padding.
__global__ __launch_bounds__(256, 2)
void kv_hmma(const float* __restrict__ k, const float* __restrict__ v)
{
    __shared__ __align__(16) __half Asm[128 * 64];   // [128 d'][64 l] rows of 128B
    __shared__ __align__(16) __half Bsm[80 * 64];    // [80 m][64 l]

    const int t = threadIdx.x;
    const int wid = t >> 5, lane = t & 31;
    const int head = blockIdx.x, chunk = blockIdx.y;
    const int b = head / H_, h = head % H_;

    uint32_t sA = smem_u32(Asm);
    uint32_t sB = smem_u32(Bsm);

    // static rows of B: row 64 = ones, rows 65..79 = zero
    for (int i = t; i < 16 * 64; i += 256) {
        int row = 64 + (i >> 6), l = i & 63;
        __half val = (row == 64) ? __float2half(1.0f) : __float2half(0.0f);
        *(__half*)((char*)Bsm + swz((uint32_t)row * 128 + l * 2)) = val;
    }

    float acc[9][4];
    #pragma unroll
    for (int n8 = 0; n8 < 9; n8++)
        #pragma unroll
        for (int r = 0; r < 4; r++) acc[n8][r] = 0.f;

    const int l2 = (t & 31) * 2;         // paired l within slab
    const int dg = t >> 5;               // 0..7
    const int d0 = dg * 8;
    const int lrow = lane & 15;
    const int lhalf = (lane >> 4) * 16;

    for (int slab = 0; slab < KVCH / 64; slab++) {
        __syncthreads();                 // prev MMA reads done (and init visible)
        int gl0 = chunk * KVCH + slab * 64 + l2;
        float s0, c0, s1, c1;
        sincosf((float)M_PI * 0.5f * (float)(gl0 + 1) / (float)L_, &s0, &c0);
        sincosf((float)M_PI * 0.5f * (float)(gl0 + 2) / (float)L_, &s1, &c1);
        size_t base0 = ((size_t)(b * L_ + gl0)) * E_ + h * HD_;
        size_t base1 = base0 + E_;
        float4 ka0 = *(const float4*)&k[base0 + d0];
        float4 ka1 = *(const float4*)&k[base0 + d0 + 4];
        float4 kb0 = *(const float4*)&k[base1 + d0];
        float4 kb1 = *(const float4*)&k[base1 + d0 + 4];
        float4 va0 = *(const float4*)&v[base0 + d0];
        float4 va1 = *(const float4*)&v[base0 + d0 + 4];
        float4 vb0 = *(const float4*)&v[base1 + d0];
        float4 vb1 = *(const float4*)&v[base1 + d0 + 4];
        float k0a[8] = {ka0.x, ka0.y, ka0.z, ka0.w, ka1.x, ka1.y, ka1.z, ka1.w};
        float k1a[8] = {kb0.x, kb0.y, kb0.z, kb0.w, kb1.x, kb1.y, kb1.z, kb1.w};
        float v0a[8] = {va0.x, va0.y, va0.z, va0.w, va1.x, va1.y, va1.z, va1.w};
        float v1a[8] = {vb0.x, vb0.y, vb0.z, vb0.w, vb1.x, vb1.y, vb1.z, vb1.w};
        #pragma unroll
        for (int d = 0; d < 8; d++) {
            __half2 hs = __floats2half2_rn(s0 * k0a[d], s1 * k1a[d]);
            *(uint32_t*)((char*)Asm + swz((uint32_t)(d0 + d) * 128 + l2 * 2)) =
                *(uint32_t*)&hs;
            __half2 hc = __floats2half2_rn(c0 * k0a[d], c1 * k1a[d]);
            *(uint32_t*)((char*)Asm + swz((uint32_t)(d0 + d + 64) * 128 + l2 * 2)) =
                *(uint32_t*)&hc;
            __half2 hv = __floats2half2_rn(v0a[d], v1a[d]);
            *(uint32_t*)((char*)Bsm + swz((uint32_t)(d0 + d) * 128 + l2 * 2)) =
                *(uint32_t*)&hv;
        }
        __syncthreads();

        #pragma unroll
        for (int kk = 0; kk < 4; kk++) {
            uint32_t a[4], bf[5][4];
            ldmatrix_x4(a, sA + swz((uint32_t)(wid * 16 + lrow) * 128 + kk * 32 + lhalf));
            #pragma unroll
            for (int nb = 0; nb < 5; nb++)
                ldmatrix_x4(bf[nb], sB + swz((uint32_t)(nb * 16 + lrow) * 128 + kk * 32 + lhalf));
            #pragma unroll
            for (int n8 = 0; n8 < 9; n8++)
                mma_fp16(acc[n8], a, bf[n8 >> 1][n8 & 1], bf[n8 >> 1][(n8 & 1) + 2]);
        }
    }

    // epilogue: partial kv + ksum
    const int qr = lane >> 2, qc = (lane & 3) * 2;
    float* kvout = &g_kvp[((size_t)(chunk * BH_ + head)) * 128 * HD_];
    #pragma unroll
    for (int n8 = 0; n8 < 8; n8++) {
        int col = n8 * 8 + qc;
        *(float2*)&kvout[(wid * 16 + qr) * HD_ + col]     = make_float2(acc[n8][0], acc[n8][1]);
        *(float2*)&kvout[(wid * 16 + qr + 8) * HD_ + col] = make_float2(acc[n8][2], acc[n8][3]);
    }
    if ((lane & 3) == 0) {
        g_ksump[(chunk * BH_ + head) * 128 + wid * 16 + qr]     = acc[8][0];
        g_ksump[(chunk * BH_ + head) * 128 + wid * 16 + qr + 8] = acc[8][2];
    }
}

// Reduce partials; emit transposed fp16 2-term kv: g_kvt2[head][m][ kvh(d) | kvl(d) ]
__global__ __launch_bounds__(256)
void kv_reduce()
{
    int head = blockIdx.x;
    int t = threadIdx.x;
    __half* kvt = g_kvt2 + (size_t)head * 64 * 256;
    for (int e = t; e < 128 * HD_; e += 256) {
        int d = e >> 6, m = e & 63;
        float s = 0.f;
        #pragma unroll
        for (int c = 0; c < NCHUNK; c++)
            s += g_kvp[((size_t)(c * BH_ + head)) * 128 * HD_ + e];
        __half hi = __float2half_rn(s);
        __half lo = __float2half_rn(s - __half2float(hi));
        kvt[m * 256 + d]       = hi;
        kvt[m * 256 + 128 + d] = lo;
    }
    if (t < 128) {
        float s = 0.f;
        #pragma unroll
        for (int c = 0; c < NCHUNK; c++)
            s += g_ksump[(c * BH_ + head) * 128 + t];
        g_ksum[head * 128 + t] = s;
    }
}

// ================= attn via HMMA =================
#define ATT_A_SM 65536            // 4 slabs * 128 rows * 128B
#define ATT_B_SM 32768            // 4 slabs * 64 rows * 128B
#define ATT_DSMEM (ATT_A_SM + ATT_B_SM + 128)

__global__ __launch_bounds__(256, 2)
void attn_hmma(const float* __restrict__ q)
{
    extern __shared__ char dsm[];
    __shared__ float ss[128], cs[128], zs[128], ks_s[128];

    const int t = threadIdx.x;
    const int wid = t >> 5, lane = t & 31;
    const int ltile = blockIdx.x;           // 0..31
    const int head  = blockIdx.y;           // 0..63
    const int b = head / H_, h = head % H_;

    char* sm = (char*)((((uintptr_t)dsm) + 127) & ~(uintptr_t)127);
    uint32_t sA = smem_u32(sm);
    uint32_t sB = sA + ATT_A_SM;

    if (t < 128) {
        int l = ltile * 128 + t;
        float ang = (float)M_PI * 0.5f * (float)(l + 1) / (float)L_;
        sincosf(ang, &ss[t], &cs[t]);
        ks_s[t] = g_ksum[head * 128 + t];
    }

    {
        const __half* kvt = g_kvt2 + (size_t)head * 64 * 256;
        #pragma unroll
        for (int j = 0; j < 8; j++) {
            int i = t + j * 256;            // 0..2047 16B chunks
            int row = i >> 5, c = i & 31;
            int slab = c >> 3, cc = c & 7;
            cp_async16(sB + slab * 8192 + swz(row * 128 + cc * 16),
                       kvt + row * 256 + c * 8);
        }
        cp_commit();
    }
    __syncthreads();

    {
        const int l_loc = t >> 1;           // 0..127
        const int halfsel = t & 1;
        int lg = ltile * 128 + l_loc;
        const float* qrow = q + ((size_t)(b * L_ + lg)) * E_ + h * HD_;
        float w = halfsel ? cs[l_loc] : ss[l_loc];
        float zpart = 0.f;
        char* aw_hi = sm + halfsel * 16384;
        char* aw_lo = sm + (2 + halfsel) * 16384;
        #pragma unroll 4
        for (int it = 0; it < 32; it++) {
            int dp = halfsel * 64 + 2 * it;
            float q0 = qrow[dp & 63];
            float q1 = qrow[(dp & 63) + 1];
            float f0 = w * q0, f1 = w * q1;
            zpart += f0 * ks_s[dp] + f1 * ks_s[dp + 1];
            __half h0 = __float2half_rn(f0), h1 = __float2half_rn(f1);
            __half e0 = __float2half_rn(f0 - __half2float(h0));
            __half e1 = __float2half_rn(f1 - __half2float(h1));
            union { __half x[2]; uint32_t u; } H, Lw;
            H.x[0] = h0; H.x[1] = h1;
            Lw.x[0] = e0; Lw.x[1] = e1;
            uint32_t off = swz((uint32_t)l_loc * 128 + (dp & 63) * 2);
            *(uint32_t*)(aw_hi + off) = H.u;
            *(uint32_t*)(aw_lo + off) = Lw.u;
        }
        zpart += __shfl_xor_sync(0xffffffffu, zpart, 1);
        if (!halfsel) zs[l_loc] = 1.f / fmaxf(zpart, EPS_);
    }

    cp_wait_group<0>();
    __syncthreads();

    const int wm = wid & 1;
    const int wn = wid >> 1;
    const int lrow = lane & 15;
    const int lhalf = (lane >> 4) * 16;

    float acc[4][2][4];
    #pragma unroll
    for (int mi = 0; mi < 4; mi++)
        #pragma unroll
        for (int hi = 0; hi < 2; hi++)
            #pragma unroll
            for (int r = 0; r < 4; r++) acc[mi][hi][r] = 0.f;

    const int As_idx[6] = {0, 1, 2, 3, 0, 1};
    const int Bs_idx[6] = {0, 1, 0, 1, 2, 3};
    #pragma unroll
    for (int p = 0; p < 6; p++) {
        uint32_t a_s = sA + As_idx[p] * 16384;
        uint32_t b_s = sB + Bs_idx[p] * 8192;
        #pragma unroll
        for (int kk = 0; kk < 4; kk++) {
            uint32_t a[4][4], bfr[4];
            #pragma unroll
            for (int mi = 0; mi < 4; mi++) {
                uint32_t off = (uint32_t)(wm * 64 + mi * 16 + lrow) * 128 + kk * 32 + lhalf;
                ldmatrix_x4(a[mi], a_s + swz(off));
            }
            {
                uint32_t off = (uint32_t)(wn * 16 + lrow) * 128 + kk * 32 + lhalf;
                ldmatrix_x4(bfr, b_s + swz(off));
            }
            #pragma unroll
            for (int mi = 0; mi < 4; mi++)
                #pragma unroll
                for (int hi = 0; hi < 2; hi++)
                    mma_fp16(acc[mi][hi], a[mi], bfr[hi], bfr[hi + 2]);
        }
    }

    const int qr = lane >> 2;
    const int qc = (lane & 3) * 2;
    #pragma unroll
    for (int mi = 0; mi < 4; mi++) {
        #pragma unroll
        for (int hi = 0; hi < 2; hi++) {
            #pragma unroll
            for (int r = 0; r < 2; r++) {
                int lloc = wm * 64 + mi * 16 + qr + r * 8;
                int n = wn * 16 + hi * 8 + qc;
                float z = zs[lloc];
                float v0 = acc[mi][hi][r * 2 + 0] * z;
                float v1 = acc[mi][hi][r * 2 + 1] * z;
                union { __half x[2]; uint32_t u; } Hh;
                Hh.x[0] = __float2half_rn(v0);
                Hh.x[1] = __float2half_rn(v1);
                __half* ob = g_attn2 + ((size_t)(b * L_ + ltile * 128 + lloc)) * KTOT
                           + h * HD_ + n;
                *(uint32_t*)(ob) = Hh.u;
            }
        }
    }
}

// ================= launcher =================
extern "C" void kernel_launch(void* const* d_in, const int* in_sizes, int n_in,
                              void* d_out, int out_size)
{
    const float* x  = (const float*)d_in[0];
    const float* Wq = (const float*)d_in[1];
    const float* bq = (const float*)d_in[2];
    const float* Wk = (const float*)d_in[3];
    const float* bk = (const float*)d_in[4];
    const float* Wv = (const float*)d_in[5];
    const float* bv = (const float*)d_in[6];
    const float* Wo = (const float*)d_in[7];
    const float* bo = (const float*)d_in[8];
    float* out = (float*)d_out;

    __half *x2, *attn2, *w2;
    float *q, *k, *v;
    cudaGetSymbolAddress((void**)&x2,    g_x2);
    cudaGetSymbolAddress((void**)&attn2, g_attn2);
    cudaGetSymbolAddress((void**)&w2,    g_w2);
    cudaGetSymbolAddress((void**)&q,     g_q);
    cudaGetSymbolAddress((void**)&k,     g_k);
    cudaGetSymbolAddress((void**)&v,     g_v);
    __half* w2o = w2 + (size_t)3 * E_ * KTOT;

    cudaFuncSetAttribute(gemm_mma,  cudaFuncAttributeMaxDynamicSharedMemorySize, GEMM_DSMEM);
    cudaFuncSetAttribute(gemm_qkv,  cudaFuncAttributeMaxDynamicSharedMemorySize, GEMM_DSMEM);
    cudaFuncSetAttribute(attn_hmma, cudaFuncAttributeMaxDynamicSharedMemorySize, ATT_DSMEM);

    // fp16 conversions
    convert_kernel<<<M_ * (E_/4) / 256, 256>>>(x, x2, M_);
    convert_w_kernel<<<dim3(E_ * (E_/4) / 256, 4), 256>>>(Wq, Wk, Wv, Wo, w2);

    // merged QKV projection
    gemm_qkv<<<dim3(3 * E_ / GBN, M_ / GBM), 256, GEMM_DSMEM>>>(
        x2, w2, bq, bk, bv, q, k, v);

    kv_hmma<<<dim3(BH_, NCHUNK), 256>>>(k, v);
    kv_reduce<<<BH_, 256>>>();
    attn_hmma<<<dim3(32, BH_), 256, ATT_DSMEM>>>(q);

    gemm_mma<<<dim3(E_ / GBN, M_ / GBM), 256, GEMM_DSMEM>>>(attn2, w2o, bo, out);
}

// round 10
// speedup vs baseline: 3.0240x; 1.1083x over previous
#include <cuda_runtime.h>
#include <cuda_fp16.h>
#include <math.h>
#include <stdint.h>

#define B_   4
#define L_   4096
#define E_   1024
#define H_   16
#define HD_  64
#define M_   (B_*L_)    // 16384 rows
#define BH_  (B_*H_)    // 64 heads
#define EPS_ 1e-4f
#define KTOT 1024       // plain 1-term fp16
#define NCHUNK 8        // kv l-chunks
#define KVCH (L_/NCHUNK) // 512

// ---------------- scratch (no allocations allowed) ----------------
__device__ __half g_x2[(size_t)M_*KTOT];
__device__ __half g_attn2[(size_t)M_*KTOT];
__device__ __half g_w2[4][(size_t)E_*KTOT];
__device__ __half g_qh[(size_t)M_*E_];
__device__ __half g_kh[(size_t)M_*E_];
__device__ __half g_vh[(size_t)M_*E_];
__device__ float g_kvp[NCHUNK*BH_*128*HD_];
__device__ float g_ksump[NCHUNK*BH_*128];
__device__ float g_ksum[BH_*128];
__device__ __half g_kvt2[(size_t)BH_*64*256];  // per head: [64 m][kvh(128) | kvl(128)]

// ================= PTX helpers (sm_80-generic only!) =================
__device__ __forceinline__ uint32_t smem_u32(const void* p) {
    uint32_t a;
    asm("{ .reg .u64 t; cvta.to.shared.u64 t, %1; cvt.u32.u64 %0, t; }" : "=r"(a) : "l"(p));
    return a;
}
__device__ __forceinline__ void cp_async16(uint32_t saddr, const void* gaddr) {
    asm volatile("cp.async.cg.shared.global [%0], [%1], 16;" :: "r"(saddr), "l"(gaddr) : "memory");
}
__device__ __forceinline__ void cp_commit() {
    asm volatile("cp.async.commit_group;" ::: "memory");
}
template<int N> __device__ __forceinline__ void cp_wait_group() {
    asm volatile("cp.async.wait_group %0;" :: "n"(N) : "memory");
}
__device__ __forceinline__ void ldmatrix_x4(uint32_t* r, uint32_t addr) {
    asm volatile("ldmatrix.sync.aligned.m8n8.x4.shared.b16 {%0,%1,%2,%3}, [%4];"
        : "=r"(r[0]), "=r"(r[1]), "=r"(r[2]), "=r"(r[3]) : "r"(addr));
}
__device__ __forceinline__ void mma_fp16(float* c, const uint32_t* a, uint32_t b0, uint32_t b1) {
    asm volatile("mma.sync.aligned.m16n8k16.row.col.f32.f16.f16.f32 "
        "{%0,%1,%2,%3}, {%4,%5,%6,%7}, {%8,%9}, {%0,%1,%2,%3};"
        : "+f"(c[0]), "+f"(c[1]), "+f"(c[2]), "+f"(c[3])
        : "r"(a[0]), "r"(a[1]), "r"(a[2]), "r"(a[3]), "r"(b0), "r"(b1));
}
__device__ __forceinline__ uint32_t swz(uint32_t off) { return off ^ ((off >> 3) & 0x70); }

// ================= fp32 -> fp16 convert =================
__global__ void convert_kernel(const float* __restrict__ in, __half* __restrict__ out, int rows)
{
    int idx = blockIdx.x * blockDim.x + threadIdx.x;          // one float4 per thread
    int total = rows * (E_ / 4);
    if (idx >= total) return;
    float4 v = *(const float4*)&in[(size_t)idx * 4];
    union { __half b[4]; uint2 u; } Hh;
    Hh.b[0] = __float2half_rn(v.x);
    Hh.b[1] = __float2half_rn(v.y);
    Hh.b[2] = __float2half_rn(v.z);
    Hh.b[3] = __float2half_rn(v.w);
    *(uint2*)&out[(size_t)idx * 4] = Hh.u;
}

// convert 4 weight matrices in one launch (blockIdx.y selects source)
__global__ void convert_w_kernel(const float* __restrict__ w0, const float* __restrict__ w1,
                                 const float* __restrict__ w2s, const float* __restrict__ w3,
                                 __half* __restrict__ out)
{
    int seg = blockIdx.y;
    const float* in = (seg == 0) ? w0 : (seg == 1) ? w1 : (seg == 2) ? w2s : w3;
    int idx = blockIdx.x * blockDim.x + threadIdx.x;
    int total = E_ * (E_ / 4);
    if (idx >= total) return;
    float4 v = *(const float4*)&in[(size_t)idx * 4];
    union { __half b[4]; uint2 u; } Hh;
    Hh.b[0] = __float2half_rn(v.x);
    Hh.b[1] = __float2half_rn(v.y);
    Hh.b[2] = __float2half_rn(v.z);
    Hh.b[3] = __float2half_rn(v.w);
    *(uint2*)&out[(size_t)seg * E_ * KTOT + (size_t)idx * 4] = Hh.u;
}

// ================= HMMA GEMM =================
// Tile 128x128x64, 8 warps, warp tile 64x32, mma.sync m16n8k16.
#define GBM 128
#define GBN 128
#define SLAB 64                 // fp16 K per slab = 128 bytes per row
#define NSLAB (KTOT/SLAB)       // 16
#define NSTG 3
#define AB_BYTES (GBM*128)      // 16384 (A tile == B tile size)
#define STG_BYTES (2*AB_BYTES)  // 32768
#define GEMM_DSMEM (NSTG*STG_BYTES + 1024)

__device__ __forceinline__ void gemm_issue_loads(
    const __half* ga, const __half* gw,
    uint32_t base, int slab, int buf, int t)
{
    int k0 = slab * SLAB;
    uint32_t stA = base + buf * STG_BYTES;
    uint32_t stW = stA + AB_BYTES;
    const __half* gak = ga + k0;
    const __half* gwk = gw + k0;
    #pragma unroll
    for (int j = 0; j < 4; j++) {
        int i = t + j * 256;            // 0..1023
        int row = i >> 3, c = i & 7;
        cp_async16(stA + swz(row * 128 + c * 16), gak + (size_t)row * KTOT + c * 8);
    }
    #pragma unroll
    for (int j = 0; j < 4; j++) {
        int i = t + j * 256;
        int row = i >> 3, c = i & 7;
        cp_async16(stW + swz(row * 128 + c * 16), gwk + (size_t)row * KTOT + c * 8);
    }
    cp_commit();
}

struct GemmFrag { float acc[4][4][4]; };

__device__ __forceinline__ void gemm_mainloop(
    const __half* ga, const __half* gw, uint32_t base, int t, GemmFrag& F)
{
    const int wid = t >> 5, lane = t & 31;
    const int wm = wid >> 2;
    const int wn = wid & 3;
    #pragma unroll
    for (int mi = 0; mi < 4; mi++)
        #pragma unroll
        for (int ni = 0; ni < 4; ni++)
            #pragma unroll
            for (int r = 0; r < 4; r++) F.acc[mi][ni][r] = 0.f;

    #pragma unroll
    for (int s = 0; s < NSTG - 1; s++) gemm_issue_loads(ga, gw, base, s, s, t);

    const int lrow = lane & 15;
    const int lhalf = (lane >> 4) * 16;

    for (int i = 0; i < NSLAB; i++) {
        cp_wait_group<NSTG - 2>();
        __syncthreads();
        if (i + NSTG - 1 < NSLAB)
            gemm_issue_loads(ga, gw, base, i + NSTG - 1, (i + NSTG - 1) % NSTG, t);
        else
            cp_commit();

        uint32_t sA = base + (i % NSTG) * STG_BYTES;
        uint32_t sB = sA + AB_BYTES;

        #pragma unroll
        for (int kk = 0; kk < 4; kk++) {
            uint32_t a[4][4], b[2][4];
            #pragma unroll
            for (int mi = 0; mi < 4; mi++) {
                uint32_t off = (uint32_t)(wm * 64 + mi * 16 + lrow) * 128 + kk * 32 + lhalf;
                ldmatrix_x4(a[mi], sA + swz(off));
            }
            #pragma unroll
            for (int nb = 0; nb < 2; nb++) {
                uint32_t off = (uint32_t)(wn * 32 + nb * 16 + lrow) * 128 + kk * 32 + lhalf;
                ldmatrix_x4(b[nb], sB + swz(off));
            }
            #pragma unroll
            for (int mi = 0; mi < 4; mi++)
                #pragma unroll
                for (int ni = 0; ni < 4; ni++) {
                    int nb = ni >> 1, hi = ni & 1;
                    mma_fp16(F.acc[mi][ni], a[mi], b[nb][hi], b[nb][hi + 2]);
                }
        }
        __syncthreads();
    }
}

// fp32 epilogue (Wo output)
__device__ __forceinline__ void gemm_epilogue_f32(
    GemmFrag& F, const float* bias, float* C, int bm, int cn, int t)
{
    const int wid = t >> 5, lane = t & 31;
    const int wm = wid >> 2, wn = wid & 3;
    const int qrow = lane >> 2;
    const int qcol = (lane & 3) * 2;
    #pragma unroll
    for (int mi = 0; mi < 4; mi++) {
        int row0 = bm + wm * 64 + mi * 16 + qrow;
        #pragma unroll
        for (int ni = 0; ni < 4; ni++) {
            int col = cn + wn * 32 + ni * 8 + qcol;
            float2 bb = *(const float2*)&bias[col];
            *(float2*)&C[(size_t)row0 * E_ + col] =
                make_float2(F.acc[mi][ni][0] + bb.x, F.acc[mi][ni][1] + bb.y);
            *(float2*)&C[(size_t)(row0 + 8) * E_ + col] =
                make_float2(F.acc[mi][ni][2] + bb.x, F.acc[mi][ni][3] + bb.y);
        }
    }
}

// fp16 epilogue (q/k/v outputs)
__device__ __forceinline__ void gemm_epilogue_f16(
    GemmFrag& F, const float* bias, __half* C, int bm, int cn, bool relu, int t)
{
    const int wid = t >> 5, lane = t & 31;
    const int wm = wid >> 2, wn = wid & 3;
    const int qrow = lane >> 2;
    const int qcol = (lane & 3) * 2;
    #pragma unroll
    for (int mi = 0; mi < 4; mi++) {
        int row0 = bm + wm * 64 + mi * 16 + qrow;
        #pragma unroll
        for (int ni = 0; ni < 4; ni++) {
            int col = cn + wn * 32 + ni * 8 + qcol;
            float2 bb = *(const float2*)&bias[col];
            float v0 = F.acc[mi][ni][0] + bb.x;
            float v1 = F.acc[mi][ni][1] + bb.y;
            float v2 = F.acc[mi][ni][2] + bb.x;
            float v3 = F.acc[mi][ni][3] + bb.y;
            if (relu) {
                v0 = fmaxf(v0, 0.f); v1 = fmaxf(v1, 0.f);
                v2 = fmaxf(v2, 0.f); v3 = fmaxf(v3, 0.f);
            }
            __half2 p01 = __floats2half2_rn(v0, v1);
            __half2 p23 = __floats2half2_rn(v2, v3);
            *(__half2*)&C[(size_t)row0 * E_ + col]       = p01;
            *(__half2*)&C[(size_t)(row0 + 8) * E_ + col] = p23;
        }
    }
}

// Merged Q/K/V projection: W2all = [Wq2; Wk2; Wv2] rows 0..3071
__global__ __launch_bounds__(256, 2)
void gemm_qkv(const __half* __restrict__ A2, const __half* __restrict__ W2all,
              const float* __restrict__ bq, const float* __restrict__ bk,
              const float* __restrict__ bv,
              __half* __restrict__ qp, __half* __restrict__ kp, __half* __restrict__ vp)
{
    extern __shared__ char dsm[];
    const int t = threadIdx.x;
    const int bm = blockIdx.y * GBM;
    const int bnG = blockIdx.x * GBN;          // 0..2944
    const int seg = bnG >> 10;                 // 0=q 1=k 2=v
    const int cn = bnG & 1023;

    uint32_t base = (smem_u32(dsm) + 1023u) & ~1023u;
    const __half* ga = A2 + (size_t)bm * KTOT;
    const __half* gw = W2all + (size_t)bnG * KTOT;

    GemmFrag F;
    gemm_mainloop(ga, gw, base, t, F);

    const float* bias = (seg == 0) ? bq : (seg == 1) ? bk : bv;
    __half* C = (seg == 0) ? qp : (seg == 1) ? kp : vp;
    gemm_epilogue_f16(F, bias, C, bm, cn, seg < 2, t);
}

// Single-output GEMM (used for Wo)
__global__ __launch_bounds__(256, 2)
void gemm_mma(const __half* __restrict__ A2, const __half* __restrict__ W2,
              const float* __restrict__ bias, float* __restrict__ C)
{
    extern __shared__ char dsm[];
    const int t = threadIdx.x;
    const int bm = blockIdx.y * GBM;
    const int bn = blockIdx.x * GBN;

    uint32_t base = (smem_u32(dsm) + 1023u) & ~1023u;
    const __half* ga = A2 + (size_t)bm * KTOT;
    const __half* gw = W2 + (size_t)bn * KTOT;

    GemmFrag F;
    gemm_mainloop(ga, gw, base, t, F);
    gemm_epilogue_f32(F, bias, C, bm, bn, t);
}

// ================= kv via HMMA =================
// Per block (head, chunk of 512 l): C[128 d'][72] = sum_l A[d'][l]*B[m][l]
// A[d'][l] = w(l,d')*k[l, d'%64] fp16 (transposed staging), B[m][l] = v[l][m] fp16.
// B row 64 = ones -> C[.,64] = ksum partial. Rows 65..79 zero padding.
__global__ __launch_bounds__(256, 2)
void kv_hmma(const __half* __restrict__ k, const __half* __restrict__ v)
{
    __shared__ __align__(16) __half Asm[128 * 64];   // [128 d'][64 l] rows of 128B
    __shared__ __align__(16) __half Bsm[80 * 64];    // [80 m][64 l]

    const int t = threadIdx.x;
    const int wid = t >> 5, lane = t & 31;
    const int head = blockIdx.x, chunk = blockIdx.y;
    const int b = head / H_, h = head % H_;

    uint32_t sA = smem_u32(Asm);
    uint32_t sB = smem_u32(Bsm);

    // static rows of B: row 64 = ones, rows 65..79 = zero
    for (int i = t; i < 16 * 64; i += 256) {
        int row = 64 + (i >> 6), l = i & 63;
        __half val = (row == 64) ? __float2half(1.0f) : __float2half(0.0f);
        *(__half*)((char*)Bsm + swz((uint32_t)row * 128 + l * 2)) = val;
    }

    float acc[9][4];
    #pragma unroll
    for (int n8 = 0; n8 < 9; n8++)
        #pragma unroll
        for (int r = 0; r < 4; r++) acc[n8][r] = 0.f;

    const int l2 = (t & 31) * 2;         // paired l within slab
    const int dg = t >> 5;               // 0..7
    const int d0 = dg * 8;
    const int lrow = lane & 15;
    const int lhalf = (lane >> 4) * 16;

    for (int slab = 0; slab < KVCH / 64; slab++) {
        __syncthreads();                 // prev MMA reads done (and init visible)
        int gl0 = chunk * KVCH + slab * 64 + l2;
        float s0, c0, s1, c1;
        sincosf((float)M_PI * 0.5f * (float)(gl0 + 1) / (float)L_, &s0, &c0);
        sincosf((float)M_PI * 0.5f * (float)(gl0 + 2) / (float)L_, &s1, &c1);
        size_t base0 = ((size_t)(b * L_ + gl0)) * E_ + h * HD_;
        size_t base1 = base0 + E_;
        // 8 halves = 16B per row
        uint4 ku0 = *(const uint4*)&k[base0 + d0];
        uint4 ku1 = *(const uint4*)&k[base1 + d0];
        uint4 vu0 = *(const uint4*)&v[base0 + d0];
        uint4 vu1 = *(const uint4*)&v[base1 + d0];
        const __half2* k0h = (const __half2*)&ku0;
        const __half2* k1h = (const __half2*)&ku1;
        const __half2* v0h = (const __half2*)&vu0;
        const __half2* v1h = (const __half2*)&vu1;
        #pragma unroll
        for (int dd = 0; dd < 4; dd++) {
            float2 k0f = __half22float2(k0h[dd]);
            float2 k1f = __half22float2(k1h[dd]);
            float2 v0f = __half22float2(v0h[dd]);
            float2 v1f = __half22float2(v1h[dd]);
            float kk0[2] = {k0f.x, k0f.y};
            float kk1[2] = {k1f.x, k1f.y};
            float vv0[2] = {v0f.x, v0f.y};
            float vv1[2] = {v1f.x, v1f.y};
            #pragma unroll
            for (int e = 0; e < 2; e++) {
                int d = dd * 2 + e;
                __half2 hs = __floats2half2_rn(s0 * kk0[e], s1 * kk1[e]);
                *(uint32_t*)((char*)Asm + swz((uint32_t)(d0 + d) * 128 + l2 * 2)) =
                    *(uint32_t*)&hs;
                __half2 hc = __floats2half2_rn(c0 * kk0[e], c1 * kk1[e]);
                *(uint32_t*)((char*)Asm + swz((uint32_t)(d0 + d + 64) * 128 + l2 * 2)) =
                    *(uint32_t*)&hc;
                __half2 hv = __floats2half2_rn(vv0[e], vv1[e]);
                *(uint32_t*)((char*)Bsm + swz((uint32_t)(d0 + d) * 128 + l2 * 2)) =
                    *(uint32_t*)&hv;
            }
        }
        __syncthreads();

        #pragma unroll
        for (int kk = 0; kk < 4; kk++) {
            uint32_t a[4], bf[5][4];
            ldmatrix_x4(a, sA + swz((uint32_t)(wid * 16 + lrow) * 128 + kk * 32 + lhalf));
            #pragma unroll
            for (int nb = 0; nb < 5; nb++)
                ldmatrix_x4(bf[nb], sB + swz((uint32_t)(nb * 16 + lrow) * 128 + kk * 32 + lhalf));
            #pragma unroll
            for (int n8 = 0; n8 < 9; n8++)
                mma_fp16(acc[n8], a, bf[n8 >> 1][n8 & 1], bf[n8 >> 1][(n8 & 1) + 2]);
        }
    }

    // epilogue: partial kv + ksum
    const int qr = lane >> 2, qc = (lane & 3) * 2;
    float* kvout = &g_kvp[((size_t)(chunk * BH_ + head)) * 128 * HD_];
    #pragma unroll
    for (int n8 = 0; n8 < 8; n8++) {
        int col = n8 * 8 + qc;
        *(float2*)&kvout[(wid * 16 + qr) * HD_ + col]     = make_float2(acc[n8][0], acc[n8][1]);
        *(float2*)&kvout[(wid * 16 + qr + 8) * HD_ + col] = make_float2(acc[n8][2], acc[n8][3]);
    }
    if ((lane & 3) == 0) {
        g_ksump[(chunk * BH_ + head) * 128 + wid * 16 + qr]     = acc[8][0];
        g_ksump[(chunk * BH_ + head) * 128 + wid * 16 + qr + 8] = acc[8][2];
    }
}

// Reduce partials; emit transposed fp16 2-term kv: g_kvt2[head][m][ kvh(d) | kvl(d) ]
__global__ __launch_bounds__(256)
void kv_reduce()
{
    int head = blockIdx.x;
    int t = threadIdx.x;
    __half* kvt = g_kvt2 + (size_t)head * 64 * 256;
    for (int e = t; e < 128 * HD_; e += 256) {
        int d = e >> 6, m = e & 63;
        float s = 0.f;
        #pragma unroll
        for (int c = 0; c < NCHUNK; c++)
            s += g_kvp[((size_t)(c * BH_ + head)) * 128 * HD_ + e];
        __half hi = __float2half_rn(s);
        __half lo = __float2half_rn(s - __half2float(hi));
        kvt[m * 256 + d]       = hi;
        kvt[m * 256 + 128 + d] = lo;
    }
    if (t < 128) {
        float s = 0.f;
        #pragma unroll
        for (int c = 0; c < NCHUNK; c++)
            s += g_ksump[(c * BH_ + head) * 128 + t];
        g_ksum[head * 128 + t] = s;
    }
}

// ================= attn via HMMA =================
// A = q_ fp16 1-term (2 slabs of k64), B = kvt2 [kvh|kvl] (4 slabs).
// Passes: (A0,B0)(A1,B1)(A0,B2)(A1,B3) = qh.kvh + qh.kvl.
#define ATT_A_SM 32768            // 2 slabs * 128 rows * 128B
#define ATT_B_SM 32768            // 4 slabs * 64 rows * 128B
#define ATT_DSMEM (ATT_A_SM + ATT_B_SM + 128)

__global__ __launch_bounds__(256, 2)
void attn_hmma(const __half* __restrict__ q)
{
    extern __shared__ char dsm[];
    __shared__ float ss[128], cs[128], zs[128], ks_s[128];

    const int t = threadIdx.x;
    const int wid = t >> 5, lane = t & 31;
    const int ltile = blockIdx.x;           // 0..31
    const int head  = blockIdx.y;           // 0..63
    const int b = head / H_, h = head % H_;

    char* sm = (char*)((((uintptr_t)dsm) + 127) & ~(uintptr_t)127);
    uint32_t sA = smem_u32(sm);
    uint32_t sB = sA + ATT_A_SM;

    if (t < 128) {
        int l = ltile * 128 + t;
        float ang = (float)M_PI * 0.5f * (float)(l + 1) / (float)L_;
        sincosf(ang, &ss[t], &cs[t]);
        ks_s[t] = g_ksum[head * 128 + t];
    }

    {
        const __half* kvt = g_kvt2 + (size_t)head * 64 * 256;
        #pragma unroll
        for (int j = 0; j < 8; j++) {
            int i = t + j * 256;            // 0..2047 16B chunks
            int row = i >> 5, c = i & 31;
            int slab = c >> 3, cc = c & 7;
            cp_async16(sB + slab * 8192 + swz(row * 128 + cc * 16),
                       kvt + row * 256 + c * 8);
        }
        cp_commit();
    }
    __syncthreads();

    {
        const int l_loc = t >> 1;           // 0..127
        const int halfsel = t & 1;
        int lg = ltile * 128 + l_loc;
        const __half* qrow = q + ((size_t)(b * L_ + lg)) * E_ + h * HD_;
        float w = halfsel ? cs[l_loc] : ss[l_loc];
        float zpart = 0.f;
        char* aw = sm + halfsel * 16384;    // slab halfsel
        #pragma unroll 4
        for (int it = 0; it < 32; it++) {
            int dp = halfsel * 64 + 2 * it;
            float2 qq = __half22float2(*(const __half2*)&qrow[dp & 63]);
            float f0 = w * qq.x, f1 = w * qq.y;
            zpart += f0 * ks_s[dp] + f1 * ks_s[dp + 1];
            __half2 Hp = __floats2half2_rn(f0, f1);
            uint32_t off = swz((uint32_t)l_loc * 128 + (dp & 63) * 2);
            *(uint32_t*)(aw + off) = *(uint32_t*)&Hp;
        }
        zpart += __shfl_xor_sync(0xffffffffu, zpart, 1);
        if (!halfsel) zs[l_loc] = 1.f / fmaxf(zpart, EPS_);
    }

    cp_wait_group<0>();
    __syncthreads();

    const int wm = wid & 1;
    const int wn = wid >> 1;
    const int lrow = lane & 15;
    const int lhalf = (lane >> 4) * 16;

    float acc[4][2][4];
    #pragma unroll
    for (int mi = 0; mi < 4; mi++)
        #pragma unroll
        for (int hi = 0; hi < 2; hi++)
            #pragma unroll
            for (int r = 0; r < 4; r++) acc[mi][hi][r] = 0.f;

    const int As_idx[4] = {0, 1, 0, 1};
    const int Bs_idx[4] = {0, 1, 2, 3};
    #pragma unroll
    for (int p = 0; p < 4; p++) {
        uint32_t a_s = sA + As_idx[p] * 16384;
        uint32_t b_s = sB + Bs_idx[p] * 8192;
        #pragma unroll
        for (int kk = 0; kk < 4; kk++) {
            uint32_t a[4][4], bfr[4];
            #pragma unroll
            for (int mi = 0; mi < 4; mi++) {
                uint32_t off = (uint32_t)(wm * 64 + mi * 16 + lrow) * 128 + kk * 32 + lhalf;
                ldmatrix_x4(a[mi], a_s + swz(off));
            }
            {
                uint32_t off = (uint32_t)(wn * 16 + lrow) * 128 + kk * 32 + lhalf;
                ldmatrix_x4(bfr, b_s + swz(off));
            }
            #pragma unroll
            for (int mi = 0; mi < 4; mi++)
                #pragma unroll
                for (int hi = 0; hi < 2; hi++)
                    mma_fp16(acc[mi][hi], a[mi], bfr[hi], bfr[hi + 2]);
        }
    }

    const int qr = lane >> 2;
    const int qc = (lane & 3) * 2;
    #pragma unroll
    for (int mi = 0; mi < 4; mi++) {
        #pragma unroll
        for (int hi = 0; hi < 2; hi++) {
            #pragma unroll
            for (int r = 0; r < 2; r++) {
                int lloc = wm * 64 + mi * 16 + qr + r * 8;
                int n = wn * 16 + hi * 8 + qc;
                float z = zs[lloc];
                __half2 Hp = __floats2half2_rn(acc[mi][hi][r * 2 + 0] * z,
                                               acc[mi][hi][r * 2 + 1] * z);
                __half* ob = g_attn2 + ((size_t)(b * L_ + ltile * 128 + lloc)) * KTOT
                           + h * HD_ + n;
                *(uint32_t*)(ob) = *(uint32_t*)&Hp;
            }
        }
    }
}

// ================= launcher =================
extern "C" void kernel_launch(void* const* d_in, const int* in_sizes, int n_in,
                              void* d_out, int out_size)
{
    const float* x  = (const float*)d_in[0];
    const float* Wq = (const float*)d_in[1];
    const float* bq = (const float*)d_in[2];
    const float* Wk = (const float*)d_in[3];
    const float* bk = (const float*)d_in[4];
    const float* Wv = (const float*)d_in[5];
    const float* bv = (const float*)d_in[6];
    const float* Wo = (const float*)d_in[7];
    const float* bo = (const float*)d_in[8];
    float* out = (float*)d_out;

    __half *x2, *attn2, *w2, *qh, *kh, *vh;
    cudaGetSymbolAddress((void**)&x2,    g_x2);
    cudaGetSymbolAddress((void**)&attn2, g_attn2);
    cudaGetSymbolAddress((void**)&w2,    g_w2);
    cudaGetSymbolAddress((void**)&qh,    g_qh);
    cudaGetSymbolAddress((void**)&kh,    g_kh);
    cudaGetSymbolAddress((void**)&vh,    g_vh);
    __half* w2o = w2 + (size_t)3 * E_ * KTOT;

    cudaFuncSetAttribute(gemm_mma,  cudaFuncAttributeMaxDynamicSharedMemorySize, GEMM_DSMEM);
    cudaFuncSetAttribute(gemm_qkv,  cudaFuncAttributeMaxDynamicSharedMemorySize, GEMM_DSMEM);
    cudaFuncSetAttribute(attn_hmma, cudaFuncAttributeMaxDynamicSharedMemorySize, ATT_DSMEM);

    // fp16 conversions
    convert_kernel<<<M_ * (E_/4) / 256, 256>>>(x, x2, M_);
    convert_w_kernel<<<dim3(E_ * (E_/4) / 256, 4), 256>>>(Wq, Wk, Wv, Wo, w2);

    // merged QKV projection (fp16 outputs)
    gemm_qkv<<<dim3(3 * E_ / GBN, M_ / GBM), 256, GEMM_DSMEM>>>(
        x2, w2, bq, bk, bv, qh, kh, vh);

    kv_hmma<<<dim3(BH_, NCHUNK), 256>>>(kh, vh);
    kv_reduce<<<BH_, 256>>>();
    attn_hmma<<<dim3(32, BH_), 256, ATT_DSMEM>>>(qh);

    gemm_mma<<<dim3(E_ / GBN, M_ / GBM), 256, GEMM_DSMEM>>>(attn2, w2o, bo, out);
}

// round 11
// speedup vs baseline: 3.1026x; 1.0260x over previous
#include <cuda_runtime.h>
#include <cuda_fp16.h>
#include <math.h>
#include <stdint.h>

#define B_   4
#define L_   4096
#define E_   1024
#define H_   16
#define HD_  64
#define M_   (B_*L_)    // 16384 rows
#define BH_  (B_*H_)    // 64 heads
#define EPS_ 1e-4f
#define KTOT 1024       // plain 1-term fp16
#define NCHUNK 16       // kv l-chunks
#define KVCH (L_/NCHUNK) // 256

// ---------------- scratch (no allocations allowed) ----------------
__device__ __half g_x2[(size_t)M_*KTOT];
__device__ __half g_attn2[(size_t)M_*KTOT];
__device__ __half g_w2[4][(size_t)E_*KTOT];
__device__ __half g_qh[(size_t)M_*E_];
__device__ __half g_kh[(size_t)M_*E_];
__device__ __half g_vh[(size_t)M_*E_];
__device__ float g_kvp[(size_t)NCHUNK*BH_*128*HD_];
__device__ float g_ksump[NCHUNK*BH_*128];
__device__ float g_ksum[BH_*128];
__device__ __half g_kvt2[(size_t)BH_*64*256];  // per head: [64 m][kvh(128) | kvl(128)]

// ================= PTX helpers (sm_80-generic only!) =================
__device__ __forceinline__ uint32_t smem_u32(const void* p) {
    uint32_t a;
    asm("{ .reg .u64 t; cvta.to.shared.u64 t, %1; cvt.u32.u64 %0, t; }" : "=r"(a) : "l"(p));
    return a;
}
__device__ __forceinline__ void cp_async16(uint32_t saddr, const void* gaddr) {
    asm volatile("cp.async.cg.shared.global [%0], [%1], 16;" :: "r"(saddr), "l"(gaddr) : "memory");
}
__device__ __forceinline__ void cp_commit() {
    asm volatile("cp.async.commit_group;" ::: "memory");
}
template<int N> __device__ __forceinline__ void cp_wait_group() {
    asm volatile("cp.async.wait_group %0;" :: "n"(N) : "memory");
}
__device__ __forceinline__ void ldmatrix_x4(uint32_t* r, uint32_t addr) {
    asm volatile("ldmatrix.sync.aligned.m8n8.x4.shared.b16 {%0,%1,%2,%3}, [%4];"
        : "=r"(r[0]), "=r"(r[1]), "=r"(r[2]), "=r"(r[3]) : "r"(addr));
}
__device__ __forceinline__ void ldmatrix_x4_trans(uint32_t* r, uint32_t addr) {
    asm volatile("ldmatrix.sync.aligned.m8n8.x4.trans.shared.b16 {%0,%1,%2,%3}, [%4];"
        : "=r"(r[0]), "=r"(r[1]), "=r"(r[2]), "=r"(r[3]) : "r"(addr));
}
__device__ __forceinline__ void mma_fp16(float* c, const uint32_t* a, uint32_t b0, uint32_t b1) {
    asm volatile("mma.sync.aligned.m16n8k16.row.col.f32.f16.f16.f32 "
        "{%0,%1,%2,%3}, {%4,%5,%6,%7}, {%8,%9}, {%0,%1,%2,%3};"
        : "+f"(c[0]), "+f"(c[1]), "+f"(c[2]), "+f"(c[3])
        : "r"(a[0]), "r"(a[1]), "r"(a[2]), "r"(a[3]), "r"(b0), "r"(b1));
}
__device__ __forceinline__ uint32_t swz(uint32_t off) { return off ^ ((off >> 3) & 0x70); }

// address for ldmatrix.x4.trans over a [row][64 halves] swizzled tile:
// mat0: rows kk*16+r,  col c0       mat1: rows kk*16+r,  col c0+8
// mat2: rows kk*16+8+r,col c0       mat3: rows kk*16+8+r,col c0+8
__device__ __forceinline__ uint32_t trans_addr(uint32_t base, int kk, int colhalf, int lane) {
    int mat = lane >> 3, r = lane & 7;
    int lrow = kk * 16 + ((mat & 2) << 2) + r;
    int cb = colhalf * 2 + ((mat & 1) << 4);
    return base + swz((uint32_t)lrow * 128 + cb);
}

// ================= fp32 -> fp16 convert =================
__global__ void convert_kernel(const float* __restrict__ in, __half* __restrict__ out, int rows)
{
    int idx = blockIdx.x * blockDim.x + threadIdx.x;          // one float4 per thread
    int total = rows * (E_ / 4);
    if (idx >= total) return;
    float4 v = *(const float4*)&in[(size_t)idx * 4];
    union { __half b[4]; uint2 u; } Hh;
    Hh.b[0] = __float2half_rn(v.x);
    Hh.b[1] = __float2half_rn(v.y);
    Hh.b[2] = __float2half_rn(v.z);
    Hh.b[3] = __float2half_rn(v.w);
    *(uint2*)&out[(size_t)idx * 4] = Hh.u;
}

// convert 4 weight matrices in one launch (blockIdx.y selects source)
__global__ void convert_w_kernel(const float* __restrict__ w0, const float* __restrict__ w1,
                                 const float* __restrict__ w2s, const float* __restrict__ w3,
                                 __half* __restrict__ out)
{
    int seg = blockIdx.y;
    const float* in = (seg == 0) ? w0 : (seg == 1) ? w1 : (seg == 2) ? w2s : w3;
    int idx = blockIdx.x * blockDim.x + threadIdx.x;
    int total = E_ * (E_ / 4);
    if (idx >= total) return;
    float4 v = *(const float4*)&in[(size_t)idx * 4];
    union { __half b[4]; uint2 u; } Hh;
    Hh.b[0] = __float2half_rn(v.x);
    Hh.b[1] = __float2half_rn(v.y);
    Hh.b[2] = __float2half_rn(v.z);
    Hh.b[3] = __float2half_rn(v.w);
    *(uint2*)&out[(size_t)seg * E_ * KTOT + (size_t)idx * 4] = Hh.u;
}

// ================= HMMA GEMM =================
// Tile 128x128x64, 8 warps, warp tile 64x32, mma.sync m16n8k16.
#define GBM 128
#define GBN 128
#define SLAB 64                 // fp16 K per slab = 128 bytes per row
#define NSLAB (KTOT/SLAB)       // 16
#define NSTG 3
#define AB_BYTES (GBM*128)      // 16384 (A tile == B tile size)
#define STG_BYTES (2*AB_BYTES)  // 32768
#define GEMM_DSMEM (NSTG*STG_BYTES + 1024)

__device__ __forceinline__ void gemm_issue_loads(
    const __half* ga, const __half* gw,
    uint32_t base, int slab, int buf, int t)
{
    int k0 = slab * SLAB;
    uint32_t stA = base + buf * STG_BYTES;
    uint32_t stW = stA + AB_BYTES;
    const __half* gak = ga + k0;
    const __half* gwk = gw + k0;
    #pragma unroll
    for (int j = 0; j < 4; j++) {
        int i = t + j * 256;            // 0..1023
        int row = i >> 3, c = i & 7;
        cp_async16(stA + swz(row * 128 + c * 16), gak + (size_t)row * KTOT + c * 8);
    }
    #pragma unroll
    for (int j = 0; j < 4; j++) {
        int i = t + j * 256;
        int row = i >> 3, c = i & 7;
        cp_async16(stW + swz(row * 128 + c * 16), gwk + (size_t)row * KTOT + c * 8);
    }
    cp_commit();
}

struct GemmFrag { float acc[4][4][4]; };

__device__ __forceinline__ void gemm_mainloop(
    const __half* ga, const __half* gw, uint32_t base, int t, GemmFrag& F)
{
    const int wid = t >> 5, lane = t & 31;
    const int wm = wid >> 2;
    const int wn = wid & 3;
    #pragma unroll
    for (int mi = 0; mi < 4; mi++)
        #pragma unroll
        for (int ni = 0; ni < 4; ni++)
            #pragma unroll
            for (int r = 0; r < 4; r++) F.acc[mi][ni][r] = 0.f;

    #pragma unroll
    for (int s = 0; s < NSTG - 1; s++) gemm_issue_loads(ga, gw, base, s, s, t);

    const int lrow = lane & 15;
    const int lhalf = (lane >> 4) * 16;

    for (int i = 0; i < NSLAB; i++) {
        cp_wait_group<NSTG - 2>();
        __syncthreads();
        if (i + NSTG - 1 < NSLAB)
            gemm_issue_loads(ga, gw, base, i + NSTG - 1, (i + NSTG - 1) % NSTG, t);
        else
            cp_commit();

        uint32_t sA = base + (i % NSTG) * STG_BYTES;
        uint32_t sB = sA + AB_BYTES;

        #pragma unroll
        for (int kk = 0; kk < 4; kk++) {
            uint32_t a[4][4], b[2][4];
            #pragma unroll
            for (int mi = 0; mi < 4; mi++) {
                uint32_t off = (uint32_t)(wm * 64 + mi * 16 + lrow) * 128 + kk * 32 + lhalf;
                ldmatrix_x4(a[mi], sA + swz(off));
            }
            #pragma unroll
            for (int nb = 0; nb < 2; nb++) {
                uint32_t off = (uint32_t)(wn * 32 + nb * 16 + lrow) * 128 + kk * 32 + lhalf;
                ldmatrix_x4(b[nb], sB + swz(off));
            }
            #pragma unroll
            for (int mi = 0; mi < 4; mi++)
                #pragma unroll
                for (int ni = 0; ni < 4; ni++) {
                    int nb = ni >> 1, hi = ni & 1;
                    mma_fp16(F.acc[mi][ni], a[mi], b[nb][hi], b[nb][hi + 2]);
                }
        }
        __syncthreads();
    }
}

// fp32 epilogue (Wo output)
__device__ __forceinline__ void gemm_epilogue_f32(
    GemmFrag& F, const float* bias, float* C, int bm, int cn, int t)
{
    const int wid = t >> 5, lane = t & 31;
    const int wm = wid >> 2, wn = wid & 3;
    const int qrow = lane >> 2;
    const int qcol = (lane & 3) * 2;
    #pragma unroll
    for (int mi = 0; mi < 4; mi++) {
        int row0 = bm + wm * 64 + mi * 16 + qrow;
        #pragma unroll
        for (int ni = 0; ni < 4; ni++) {
            int col = cn + wn * 32 + ni * 8 + qcol;
            float2 bb = *(const float2*)&bias[col];
            *(float2*)&C[(size_t)row0 * E_ + col] =
                make_float2(F.acc[mi][ni][0] + bb.x, F.acc[mi][ni][1] + bb.y);
            *(float2*)&C[(size_t)(row0 + 8) * E_ + col] =
                make_float2(F.acc[mi][ni][2] + bb.x, F.acc[mi][ni][3] + bb.y);
        }
    }
}

// fp16 epilogue (q/k/v outputs)
__device__ __forceinline__ void gemm_epilogue_f16(
    GemmFrag& F, const float* bias, __half* C, int bm, int cn, bool relu, int t)
{
    const int wid = t >> 5, lane = t & 31;
    const int wm = wid >> 2, wn = wid & 3;
    const int qrow = lane >> 2;
    const int qcol = (lane & 3) * 2;
    #pragma unroll
    for (int mi = 0; mi < 4; mi++) {
        int row0 = bm + wm * 64 + mi * 16 + qrow;
        #pragma unroll
        for (int ni = 0; ni < 4; ni++) {
            int col = cn + wn * 32 + ni * 8 + qcol;
            float2 bb = *(const float2*)&bias[col];
            float v0 = F.acc[mi][ni][0] + bb.x;
            float v1 = F.acc[mi][ni][1] + bb.y;
            float v2 = F.acc[mi][ni][2] + bb.x;
            float v3 = F.acc[mi][ni][3] + bb.y;
            if (relu) {
                v0 = fmaxf(v0, 0.f); v1 = fmaxf(v1, 0.f);
                v2 = fmaxf(v2, 0.f); v3 = fmaxf(v3, 0.f);
            }
            __half2 p01 = __floats2half2_rn(v0, v1);
            __half2 p23 = __floats2half2_rn(v2, v3);
            *(__half2*)&C[(size_t)row0 * E_ + col]       = p01;
            *(__half2*)&C[(size_t)(row0 + 8) * E_ + col] = p23;
        }
    }
}

// Merged Q/K/V projection: W2all = [Wq2; Wk2; Wv2] rows 0..3071
__global__ __launch_bounds__(256, 2)
void gemm_qkv(const __half* __restrict__ A2, const __half* __restrict__ W2all,
              const float* __restrict__ bq, const float* __restrict__ bk,
              const float* __restrict__ bv,
              __half* __restrict__ qp, __half* __restrict__ kp, __half* __restrict__ vp)
{
    extern __shared__ char dsm[];
    const int t = threadIdx.x;
    const int bm = blockIdx.y * GBM;
    const int bnG = blockIdx.x * GBN;          // 0..2944
    const int seg = bnG >> 10;                 // 0=q 1=k 2=v
    const int cn = bnG & 1023;

    uint32_t base = (smem_u32(dsm) + 1023u) & ~1023u;
    const __half* ga = A2 + (size_t)bm * KTOT;
    const __half* gw = W2all + (size_t)bnG * KTOT;

    GemmFrag F;
    gemm_mainloop(ga, gw, base, t, F);

    const float* bias = (seg == 0) ? bq : (seg == 1) ? bk : bv;
    __half* C = (seg == 0) ? qp : (seg == 1) ? kp : vp;
    gemm_epilogue_f16(F, bias, C, bm, cn, seg < 2, t);
}

// Single-output GEMM (used for Wo)
__global__ __launch_bounds__(256, 2)
void gemm_mma(const __half* __restrict__ A2, const __half* __restrict__ W2,
              const float* __restrict__ bias, float* __restrict__ C)
{
    extern __shared__ char dsm[];
    const int t = threadIdx.x;
    const int bm = blockIdx.y * GBM;
    const int bn = blockIdx.x * GBN;

    uint32_t base = (smem_u32(dsm) + 1023u) & ~1023u;
    const __half* ga = A2 + (size_t)bm * KTOT;
    const __half* gw = W2 + (size_t)bn * KTOT;

    GemmFrag F;
    gemm_mainloop(ga, gw, base, t, F);
    gemm_epilogue_f32(F, bias, C, bm, bn, t);
}

// ================= kv via HMMA (ldmatrix.trans, zero staging) =================
// Per block (head, chunk of 256 l): C[128 d'][64 m] += A[d'][l]*B[l][m]
// k,v tiles cp.async'd RAW as [l][64] fp16 rows (128B). A-fragments via
// ldmatrix.trans of k + half2 sin/cos scale; B via ldmatrix.trans of v.
// ksum via constant all-ones B fragment (extra mma per kk).
__global__ __launch_bounds__(256, 2)
void kv_hmma(const __half* __restrict__ k, const __half* __restrict__ v)
{
    __shared__ __align__(16) __half Ksm[2][64 * 64];
    __shared__ __align__(16) __half Vsm[2][64 * 64];
    __shared__ __half2 wsin[KVCH / 2], wcos[KVCH / 2];   // 128 pairs each

    const int t = threadIdx.x;
    const int wid = t >> 5, lane = t & 31;
    const int head = blockIdx.x, chunk = blockIdx.y;
    const int b = head / H_, h = head % H_;

    if (t < KVCH / 2) {
        int l0 = chunk * KVCH + t * 2;
        float s0, c0, s1, c1;
        sincosf((float)M_PI * 0.5f * (float)(l0 + 1) / (float)L_, &s0, &c0);
        sincosf((float)M_PI * 0.5f * (float)(l0 + 2) / (float)L_, &s1, &c1);
        wsin[t] = __floats2half2_rn(s0, s1);
        wcos[t] = __floats2half2_rn(c0, c1);
    }

    const __half* kbase = k + ((size_t)(b * L_ + chunk * KVCH)) * E_ + h * HD_;
    const __half* vbase = v + ((size_t)(b * L_ + chunk * KVCH)) * E_ + h * HD_;

    auto issue = [&](int slab, int buf) {
        uint32_t sK = smem_u32(Ksm[buf]);
        uint32_t sV = smem_u32(Vsm[buf]);
        #pragma unroll
        for (int j = 0; j < 4; j++) {
            int i = t + j * 256;            // 0..1023: first 512 = k, next = v
            int idx = i & 511;
            int row = idx >> 3, c = idx & 7;
            const __half* src = ((i >> 9) ? vbase : kbase)
                              + (size_t)(slab * 64 + row) * E_ + c * 8;
            uint32_t dst = ((i >> 9) ? sV : sK) + swz((uint32_t)row * 128 + c * 16);
            cp_async16(dst, src);
        }
        cp_commit();
    };

    float acc[9][4];
    #pragma unroll
    for (int n8 = 0; n8 < 9; n8++)
        #pragma unroll
        for (int r = 0; r < 4; r++) acc[n8][r] = 0.f;

    issue(0, 0);
    const uint32_t ONES = 0x3C003C00u;
    const int d0 = (wid & 3) * 16;

    #pragma unroll
    for (int slab = 0; slab < KVCH / 64; slab++) {     // 4
        if (slab + 1 < KVCH / 64) {
            issue(slab + 1, (slab + 1) & 1);
            cp_wait_group<1>();
        } else {
            cp_wait_group<0>();
        }
        __syncthreads();
        uint32_t sK = smem_u32(Ksm[slab & 1]);
        uint32_t sV = smem_u32(Vsm[slab & 1]);
        const __half2* wsel = (wid < 4) ? wsin : wcos;
        #pragma unroll
        for (int kk = 0; kk < 4; kk++) {
            uint32_t a[4], bf[4][4];
            ldmatrix_x4_trans(a, trans_addr(sK, kk, d0, lane));
            #pragma unroll
            for (int nb = 0; nb < 4; nb++)
                ldmatrix_x4_trans(bf[nb], trans_addr(sV, kk, nb * 16, lane));
            __half2 w0 = wsel[slab * 32 + kk * 8 + (lane & 3)];
            __half2 w1 = wsel[slab * 32 + kk * 8 + (lane & 3) + 4];
            __half2* ah = (__half2*)a;
            ah[0] = __hmul2(ah[0], w0);
            ah[1] = __hmul2(ah[1], w0);
            ah[2] = __hmul2(ah[2], w1);
            ah[3] = __hmul2(ah[3], w1);
            #pragma unroll
            for (int n8 = 0; n8 < 8; n8++)
                mma_fp16(acc[n8], a, bf[n8 >> 1][n8 & 1], bf[n8 >> 1][(n8 & 1) + 2]);
            mma_fp16(acc[8], a, ONES, ONES);
        }
        __syncthreads();
    }

    // epilogue: partial kv + ksum
    const int qr = lane >> 2, qc = (lane & 3) * 2;
    float* kvout = &g_kvp[((size_t)(chunk * BH_ + head)) * 128 * HD_];
    #pragma unroll
    for (int n8 = 0; n8 < 8; n8++) {
        int col = n8 * 8 + qc;
        *(float2*)&kvout[(wid * 16 + qr) * HD_ + col]     = make_float2(acc[n8][0], acc[n8][1]);
        *(float2*)&kvout[(wid * 16 + qr + 8) * HD_ + col] = make_float2(acc[n8][2], acc[n8][3]);
    }
    if ((lane & 3) == 0) {
        g_ksump[(chunk * BH_ + head) * 128 + wid * 16 + qr]     = acc[8][0];
        g_ksump[(chunk * BH_ + head) * 128 + wid * 16 + qr + 8] = acc[8][2];
    }
}

// Reduce partials; emit transposed fp16 2-term kv: g_kvt2[head][m][ kvh(d) | kvl(d) ]
__global__ __launch_bounds__(256)
void kv_reduce()
{
    int head = blockIdx.x;
    int t = threadIdx.x;
    __half* kvt = g_kvt2 + (size_t)head * 64 * 256;
    for (int e = t; e < 128 * HD_; e += 256) {
        int d = e >> 6, m = e & 63;
        float s = 0.f;
        #pragma unroll
        for (int c = 0; c < NCHUNK; c++)
            s += g_kvp[((size_t)(c * BH_ + head)) * 128 * HD_ + e];
        __half hi = __float2half_rn(s);
        __half lo = __float2half_rn(s - __half2float(hi));
        kvt[m * 256 + d]       = hi;
        kvt[m * 256 + 128 + d] = lo;
    }
    if (t < 128) {
        float s = 0.f;
        #pragma unroll
        for (int c = 0; c < NCHUNK; c++)
            s += g_ksump[(c * BH_ + head) * 128 + t];
        g_ksum[head * 128 + t] = s;
    }
}

// ================= attn via HMMA =================
// A = q_ fp16 1-term (2 slabs of k64), B = kvt2 [kvh|kvl] (4 slabs).
// Passes: (A0,B0)(A1,B1)(A0,B2)(A1,B3) = qh.kvh + qh.kvl.
#define ATT_A_SM 32768            // 2 slabs * 128 rows * 128B
#define ATT_B_SM 32768            // 4 slabs * 64 rows * 128B
#define ATT_DSMEM (ATT_A_SM + ATT_B_SM + 128)

__global__ __launch_bounds__(256, 2)
void attn_hmma(const __half* __restrict__ q)
{
    extern __shared__ char dsm[];
    __shared__ float ss[128], cs[128], zs[128], ks_s[128];

    const int t = threadIdx.x;
    const int wid = t >> 5, lane = t & 31;
    const int ltile = blockIdx.x;           // 0..31
    const int head  = blockIdx.y;           // 0..63
    const int b = head / H_, h = head % H_;

    char* sm = (char*)((((uintptr_t)dsm) + 127) & ~(uintptr_t)127);
    uint32_t sA = smem_u32(sm);
    uint32_t sB = sA + ATT_A_SM;

    if (t < 128) {
        int l = ltile * 128 + t;
        float ang = (float)M_PI * 0.5f * (float)(l + 1) / (float)L_;
        sincosf(ang, &ss[t], &cs[t]);
        ks_s[t] = g_ksum[head * 128 + t];
    }

    {
        const __half* kvt = g_kvt2 + (size_t)head * 64 * 256;
        #pragma unroll
        for (int j = 0; j < 8; j++) {
            int i = t + j * 256;            // 0..2047 16B chunks
            int row = i >> 5, c = i & 31;
            int slab = c >> 3, cc = c & 7;
            cp_async16(sB + slab * 8192 + swz(row * 128 + cc * 16),
                       kvt + row * 256 + c * 8);
        }
        cp_commit();
    }
    __syncthreads();

    {
        const int l_loc = t >> 1;           // 0..127
        const int halfsel = t & 1;
        int lg = ltile * 128 + l_loc;
        const __half* qrow = q + ((size_t)(b * L_ + lg)) * E_ + h * HD_;
        float w = halfsel ? cs[l_loc] : ss[l_loc];
        float zpart = 0.f;
        char* aw = sm + halfsel * 16384;    // slab halfsel
        #pragma unroll 4
        for (int it = 0; it < 32; it++) {
            int dp = halfsel * 64 + 2 * it;
            float2 qq = __half22float2(*(const __half2*)&qrow[dp & 63]);
            float f0 = w * qq.x, f1 = w * qq.y;
            zpart += f0 * ks_s[dp] + f1 * ks_s[dp + 1];
            __half2 Hp = __floats2half2_rn(f0, f1);
            uint32_t off = swz((uint32_t)l_loc * 128 + (dp & 63) * 2);
            *(uint32_t*)(aw + off) = *(uint32_t*)&Hp;
        }
        zpart += __shfl_xor_sync(0xffffffffu, zpart, 1);
        if (!halfsel) zs[l_loc] = 1.f / fmaxf(zpart, EPS_);
    }

    cp_wait_group<0>();
    __syncthreads();

    const int wm = wid & 1;
    const int wn = wid >> 1;
    const int lrow = lane & 15;
    const int lhalf = (lane >> 4) * 16;

    float acc[4][2][4];
    #pragma unroll
    for (int mi = 0; mi < 4; mi++)
        #pragma unroll
        for (int hi = 0; hi < 2; hi++)
            #pragma unroll
            for (int r = 0; r < 4; r++) acc[mi][hi][r] = 0.f;

    const int As_idx[4] = {0, 1, 0, 1};
    const int Bs_idx[4] = {0, 1, 2, 3};
    #pragma unroll
    for (int p = 0; p < 4; p++) {
        uint32_t a_s = sA + As_idx[p] * 16384;
        uint32_t b_s = sB + Bs_idx[p] * 8192;
        #pragma unroll
        for (int kk = 0; kk < 4; kk++) {
            uint32_t a[4][4], bfr[4];
            #pragma unroll
            for (int mi = 0; mi < 4; mi++) {
                uint32_t off = (uint32_t)(wm * 64 + mi * 16 + lrow) * 128 + kk * 32 + lhalf;
                ldmatrix_x4(a[mi], a_s + swz(off));
            }
            {
                uint32_t off = (uint32_t)(wn * 16 + lrow) * 128 + kk * 32 + lhalf;
                ldmatrix_x4(bfr, b_s + swz(off));
            }
            #pragma unroll
            for (int mi = 0; mi < 4; mi++)
                #pragma unroll
                for (int hi = 0; hi < 2; hi++)
                    mma_fp16(acc[mi][hi], a[mi], bfr[hi], bfr[hi + 2]);
        }
    }

    const int qr = lane >> 2;
    const int qc = (lane & 3) * 2;
    #pragma unroll
    for (int mi = 0; mi < 4; mi++) {
        #pragma unroll
        for (int hi = 0; hi < 2; hi++) {
            #pragma unroll
            for (int r = 0; r < 2; r++) {
                int lloc = wm * 64 + mi * 16 + qr + r * 8;
                int n = wn * 16 + hi * 8 + qc;
                float z = zs[lloc];
                __half2 Hp = __floats2half2_rn(acc[mi][hi][r * 2 + 0] * z,
                                               acc[mi][hi][r * 2 + 1] * z);
                __half* ob = g_attn2 + ((size_t)(b * L_ + ltile * 128 + lloc)) * KTOT
                           + h * HD_ + n;
                *(uint32_t*)(ob) = *(uint32_t*)&Hp;
            }
        }
    }
}

// ================= launcher =================
extern "C" void kernel_launch(void* const* d_in, const int* in_sizes, int n_in,
                              void* d_out, int out_size)
{
    const float* x  = (const float*)d_in[0];
    const float* Wq = (const float*)d_in[1];
    const float* bq = (const float*)d_in[2];
    const float* Wk = (const float*)d_in[3];
    const float* bk = (const float*)d_in[4];
    const float* Wv = (const float*)d_in[5];
    const float* bv = (const float*)d_in[6];
    const float* Wo = (const float*)d_in[7];
    const float* bo = (const float*)d_in[8];
    float* out = (float*)d_out;

    __half *x2, *attn2, *w2, *qh, *kh, *vh;
    cudaGetSymbolAddress((void**)&x2,    g_x2);
    cudaGetSymbolAddress((void**)&attn2, g_attn2);
    cudaGetSymbolAddress((void**)&w2,    g_w2);
    cudaGetSymbolAddress((void**)&qh,    g_qh);
    cudaGetSymbolAddress((void**)&kh,    g_kh);
    cudaGetSymbolAddress((void**)&vh,    g_vh);
    __half* w2o = w2 + (size_t)3 * E_ * KTOT;

    cudaFuncSetAttribute(gemm_mma,  cudaFuncAttributeMaxDynamicSharedMemorySize, GEMM_DSMEM);
    cudaFuncSetAttribute(gemm_qkv,  cudaFuncAttributeMaxDynamicSharedMemorySize, GEMM_DSMEM);
    cudaFuncSetAttribute(attn_hmma, cudaFuncAttributeMaxDynamicSharedMemorySize, ATT_DSMEM);

    // fp16 conversions
    convert_kernel<<<M_ * (E_/4) / 256, 256>>>(x, x2, M_);
    convert_w_kernel<<<dim3(E_ * (E_/4) / 256, 4), 256>>>(Wq, Wk, Wv, Wo, w2);

    // merged QKV projection (fp16 outputs)
    gemm_qkv<<<dim3(3 * E_ / GBN, M_ / GBM), 256, GEMM_DSMEM>>>(
        x2, w2, bq, bk, bv, qh, kh, vh);

    kv_hmma<<<dim3(BH_, NCHUNK), 256>>>(kh, vh);
    kv_reduce<<<BH_, 256>>>();
    attn_hmma<<<dim3(32, BH_), 256, ATT_DSMEM>>>(qh);

    gemm_mma<<<dim3(E_ / GBN, M_ / GBM), 256, GEMM_DSMEM>>>(attn2, w2o, bo, out);
}

// round 12
// speedup vs baseline: 3.3239x; 1.0713x over previous
#include <cuda_runtime.h>
#include <cuda_fp16.h>
#include <math.h>
#include <stdint.h>

#define B_   4
#define L_   4096
#define E_   1024
#define H_   16
#define HD_  64
#define M_   (B_*L_)    // 16384 rows
#define BH_  (B_*H_)    // 64 heads
#define EPS_ 1e-4f
#define KTOT 1024       // plain 1-term fp16
#define NCHUNK 16       // kv l-chunks
#define KVCH (L_/NCHUNK) // 256

// ---------------- scratch (no allocations allowed) ----------------
__device__ __half g_x2[(size_t)M_*KTOT];
__device__ __half g_attn2[(size_t)M_*KTOT];
__device__ __half g_w2[4][(size_t)E_*KTOT];
__device__ __half g_qh[(size_t)M_*E_];
__device__ __half g_kh[(size_t)M_*E_];
__device__ __half g_vh[(size_t)M_*E_];
__device__ float g_kvp[(size_t)NCHUNK*BH_*128*HD_];
__device__ float g_ksump[NCHUNK*BH_*128];
__device__ float g_ksum[BH_*128];
__device__ __half g_kvt[(size_t)BH_*128*64];  // [head][slab(2)][m(64)][d(64)] fp16

// ================= PTX helpers (sm_80-generic only!) =================
__device__ __forceinline__ uint32_t smem_u32(const void* p) {
    uint32_t a;
    asm("{ .reg .u64 t; cvta.to.shared.u64 t, %1; cvt.u32.u64 %0, t; }" : "=r"(a) : "l"(p));
    return a;
}
__device__ __forceinline__ void cp_async16(uint32_t saddr, const void* gaddr) {
    asm volatile("cp.async.cg.shared.global [%0], [%1], 16;" :: "r"(saddr), "l"(gaddr) : "memory");
}
__device__ __forceinline__ void cp_commit() {
    asm volatile("cp.async.commit_group;" ::: "memory");
}
template<int N> __device__ __forceinline__ void cp_wait_group() {
    asm volatile("cp.async.wait_group %0;" :: "n"(N) : "memory");
}
__device__ __forceinline__ void ldmatrix_x4(uint32_t* r, uint32_t addr) {
    asm volatile("ldmatrix.sync.aligned.m8n8.x4.shared.b16 {%0,%1,%2,%3}, [%4];"
        : "=r"(r[0]), "=r"(r[1]), "=r"(r[2]), "=r"(r[3]) : "r"(addr));
}
__device__ __forceinline__ void ldmatrix_x4_trans(uint32_t* r, uint32_t addr) {
    asm volatile("ldmatrix.sync.aligned.m8n8.x4.trans.shared.b16 {%0,%1,%2,%3}, [%4];"
        : "=r"(r[0]), "=r"(r[1]), "=r"(r[2]), "=r"(r[3]) : "r"(addr));
}
__device__ __forceinline__ void mma_fp16(float* c, const uint32_t* a, uint32_t b0, uint32_t b1) {
    asm volatile("mma.sync.aligned.m16n8k16.row.col.f32.f16.f16.f32 "
        "{%0,%1,%2,%3}, {%4,%5,%6,%7}, {%8,%9}, {%0,%1,%2,%3};"
        : "+f"(c[0]), "+f"(c[1]), "+f"(c[2]), "+f"(c[3])
        : "r"(a[0]), "r"(a[1]), "r"(a[2]), "r"(a[3]), "r"(b0), "r"(b1));
}
__device__ __forceinline__ uint32_t swz(uint32_t off) { return off ^ ((off >> 3) & 0x70); }

// address for ldmatrix.x4.trans over a [row][64 halves] swizzled tile
__device__ __forceinline__ uint32_t trans_addr(uint32_t base, int kk, int colhalf, int lane) {
    int mat = lane >> 3, r = lane & 7;
    int lrow = kk * 16 + ((mat & 2) << 2) + r;
    int cb = colhalf * 2 + ((mat & 1) << 4);
    return base + swz((uint32_t)lrow * 128 + cb);
}

// ================= merged fp32 -> fp16 convert (x + 4 weights) =================
// blocks [0,16384): x ; [16384, 16384+4*1024): weights
__global__ void convert_all(const float* __restrict__ x,
                            const float* __restrict__ w0, const float* __restrict__ w1,
                            const float* __restrict__ w2s, const float* __restrict__ w3,
                            __half* __restrict__ x2, __half* __restrict__ wout)
{
    int bid = blockIdx.x;
    const float* in;
    __half* out;
    int idx;
    if (bid < 16384) {
        in = x; out = g_x2;   // == x2
        idx = bid * 256 + threadIdx.x;
    } else {
        int wb = bid - 16384;
        int seg = wb >> 10;
        in = (seg == 0) ? w0 : (seg == 1) ? w1 : (seg == 2) ? w2s : w3;
        out = wout + (size_t)seg * E_ * KTOT;
        idx = (wb & 1023) * 256 + threadIdx.x;
    }
    float4 v = *(const float4*)&in[(size_t)idx * 4];
    union { __half b[4]; uint2 u; } Hh;
    Hh.b[0] = __float2half_rn(v.x);
    Hh.b[1] = __float2half_rn(v.y);
    Hh.b[2] = __float2half_rn(v.z);
    Hh.b[3] = __float2half_rn(v.w);
    *(uint2*)&out[(size_t)idx * 4] = Hh.u;
}

// ================= HMMA GEMM =================
// Tile 128x128x64, 8 warps, warp tile 64x32, mma.sync m16n8k16.
#define GBM 128
#define GBN 128
#define SLAB 64                 // fp16 K per slab = 128 bytes per row
#define NSLAB (KTOT/SLAB)       // 16
#define NSTG 3
#define AB_BYTES (GBM*128)      // 16384 (A tile == B tile size)
#define STG_BYTES (2*AB_BYTES)  // 32768
#define GEMM_DSMEM (NSTG*STG_BYTES + 1024)

__device__ __forceinline__ void gemm_issue_loads(
    const __half* ga, const __half* gw,
    uint32_t base, int slab, int buf, int t)
{
    int k0 = slab * SLAB;
    uint32_t stA = base + buf * STG_BYTES;
    uint32_t stW = stA + AB_BYTES;
    const __half* gak = ga + k0;
    const __half* gwk = gw + k0;
    #pragma unroll
    for (int j = 0; j < 4; j++) {
        int i = t + j * 256;            // 0..1023
        int row = i >> 3, c = i & 7;
        cp_async16(stA + swz(row * 128 + c * 16), gak + (size_t)row * KTOT + c * 8);
    }
    #pragma unroll
    for (int j = 0; j < 4; j++) {
        int i = t + j * 256;
        int row = i >> 3, c = i & 7;
        cp_async16(stW + swz(row * 128 + c * 16), gwk + (size_t)row * KTOT + c * 8);
    }
    cp_commit();
}

struct GemmFrag { float acc[4][4][4]; };

__device__ __forceinline__ void gemm_mainloop(
    const __half* ga, const __half* gw, uint32_t base, int t, GemmFrag& F)
{
    const int wid = t >> 5, lane = t & 31;
    const int wm = wid >> 2;
    const int wn = wid & 3;
    #pragma unroll
    for (int mi = 0; mi < 4; mi++)
        #pragma unroll
        for (int ni = 0; ni < 4; ni++)
            #pragma unroll
            for (int r = 0; r < 4; r++) F.acc[mi][ni][r] = 0.f;

    #pragma unroll
    for (int s = 0; s < NSTG - 1; s++) gemm_issue_loads(ga, gw, base, s, s, t);

    const int lrow = lane & 15;
    const int lhalf = (lane >> 4) * 16;

    for (int i = 0; i < NSLAB; i++) {
        cp_wait_group<NSTG - 2>();
        __syncthreads();
        if (i + NSTG - 1 < NSLAB)
            gemm_issue_loads(ga, gw, base, i + NSTG - 1, (i + NSTG - 1) % NSTG, t);
        else
            cp_commit();

        uint32_t sA = base + (i % NSTG) * STG_BYTES;
        uint32_t sB = sA + AB_BYTES;

        #pragma unroll
        for (int kk = 0; kk < 4; kk++) {
            uint32_t a[4][4], b[2][4];
            #pragma unroll
            for (int mi = 0; mi < 4; mi++) {
                uint32_t off = (uint32_t)(wm * 64 + mi * 16 + lrow) * 128 + kk * 32 + lhalf;
                ldmatrix_x4(a[mi], sA + swz(off));
            }
            #pragma unroll
            for (int nb = 0; nb < 2; nb++) {
                uint32_t off = (uint32_t)(wn * 32 + nb * 16 + lrow) * 128 + kk * 32 + lhalf;
                ldmatrix_x4(b[nb], sB + swz(off));
            }
            #pragma unroll
            for (int mi = 0; mi < 4; mi++)
                #pragma unroll
                for (int ni = 0; ni < 4; ni++) {
                    int nb = ni >> 1, hi = ni & 1;
                    mma_fp16(F.acc[mi][ni], a[mi], b[nb][hi], b[nb][hi + 2]);
                }
        }
        __syncthreads();
    }
}

// fp32 epilogue (Wo output)
__device__ __forceinline__ void gemm_epilogue_f32(
    GemmFrag& F, const float* bias, float* C, int bm, int cn, int t)
{
    const int wid = t >> 5, lane = t & 31;
    const int wm = wid >> 2, wn = wid & 3;
    const int qrow = lane >> 2;
    const int qcol = (lane & 3) * 2;
    #pragma unroll
    for (int mi = 0; mi < 4; mi++) {
        int row0 = bm + wm * 64 + mi * 16 + qrow;
        #pragma unroll
        for (int ni = 0; ni < 4; ni++) {
            int col = cn + wn * 32 + ni * 8 + qcol;
            float2 bb = *(const float2*)&bias[col];
            *(float2*)&C[(size_t)row0 * E_ + col] =
                make_float2(F.acc[mi][ni][0] + bb.x, F.acc[mi][ni][1] + bb.y);
            *(float2*)&C[(size_t)(row0 + 8) * E_ + col] =
                make_float2(F.acc[mi][ni][2] + bb.x, F.acc[mi][ni][3] + bb.y);
        }
    }
}

// fp16 epilogue (q/k/v outputs)
__device__ __forceinline__ void gemm_epilogue_f16(
    GemmFrag& F, const float* bias, __half* C, int bm, int cn, bool relu, int t)
{
    const int wid = t >> 5, lane = t & 31;
    const int wm = wid >> 2, wn = wid & 3;
    const int qrow = lane >> 2;
    const int qcol = (lane & 3) * 2;
    #pragma unroll
    for (int mi = 0; mi < 4; mi++) {
        int row0 = bm + wm * 64 + mi * 16 + qrow;
        #pragma unroll
        for (int ni = 0; ni < 4; ni++) {
            int col = cn + wn * 32 + ni * 8 + qcol;
            float2 bb = *(const float2*)&bias[col];
            float v0 = F.acc[mi][ni][0] + bb.x;
            float v1 = F.acc[mi][ni][1] + bb.y;
            float v2 = F.acc[mi][ni][2] + bb.x;
            float v3 = F.acc[mi][ni][3] + bb.y;
            if (relu) {
                v0 = fmaxf(v0, 0.f); v1 = fmaxf(v1, 0.f);
                v2 = fmaxf(v2, 0.f); v3 = fmaxf(v3, 0.f);
            }
            __half2 p01 = __floats2half2_rn(v0, v1);
            __half2 p23 = __floats2half2_rn(v2, v3);
            *(__half2*)&C[(size_t)row0 * E_ + col]       = p01;
            *(__half2*)&C[(size_t)(row0 + 8) * E_ + col] = p23;
        }
    }
}

// Merged Q/K/V projection: W2all = [Wq2; Wk2; Wv2] rows 0..3071
__global__ __launch_bounds__(256, 2)
void gemm_qkv(const __half* __restrict__ A2, const __half* __restrict__ W2all,
              const float* __restrict__ bq, const float* __restrict__ bk,
              const float* __restrict__ bv,
              __half* __restrict__ qp, __half* __restrict__ kp, __half* __restrict__ vp)
{
    extern __shared__ char dsm[];
    const int t = threadIdx.x;
    const int bm = blockIdx.y * GBM;
    const int bnG = blockIdx.x * GBN;          // 0..2944
    const int seg = bnG >> 10;                 // 0=q 1=k 2=v
    const int cn = bnG & 1023;

    uint32_t base = (smem_u32(dsm) + 1023u) & ~1023u;
    const __half* ga = A2 + (size_t)bm * KTOT;
    const __half* gw = W2all + (size_t)bnG * KTOT;

    GemmFrag F;
    gemm_mainloop(ga, gw, base, t, F);

    const float* bias = (seg == 0) ? bq : (seg == 1) ? bk : bv;
    __half* C = (seg == 0) ? qp : (seg == 1) ? kp : vp;
    gemm_epilogue_f16(F, bias, C, bm, cn, seg < 2, t);
}

// Single-output GEMM (used for Wo)
__global__ __launch_bounds__(256, 2)
void gemm_mma(const __half* __restrict__ A2, const __half* __restrict__ W2,
              const float* __restrict__ bias, float* __restrict__ C)
{
    extern __shared__ char dsm[];
    const int t = threadIdx.x;
    const int bm = blockIdx.y * GBM;
    const int bn = blockIdx.x * GBN;

    uint32_t base = (smem_u32(dsm) + 1023u) & ~1023u;
    const __half* ga = A2 + (size_t)bm * KTOT;
    const __half* gw = W2 + (size_t)bn * KTOT;

    GemmFrag F;
    gemm_mainloop(ga, gw, base, t, F);
    gemm_epilogue_f32(F, bias, C, bm, bn, t);
}

// ================= kv via HMMA (ldmatrix.trans, zero staging) =================
__global__ __launch_bounds__(256, 2)
void kv_hmma(const __half* __restrict__ k, const __half* __restrict__ v)
{
    __shared__ __align__(16) __half Ksm[2][64 * 64];
    __shared__ __align__(16) __half Vsm[2][64 * 64];
    __shared__ __half2 wsin[KVCH / 2], wcos[KVCH / 2];   // 128 pairs each

    const int t = threadIdx.x;
    const int wid = t >> 5, lane = t & 31;
    const int head = blockIdx.x, chunk = blockIdx.y;
    const int b = head / H_, h = head % H_;

    if (t < KVCH / 2) {
        int l0 = chunk * KVCH + t * 2;
        float s0, c0, s1, c1;
        sincosf((float)M_PI * 0.5f * (float)(l0 + 1) / (float)L_, &s0, &c0);
        sincosf((float)M_PI * 0.5f * (float)(l0 + 2) / (float)L_, &s1, &c1);
        wsin[t] = __floats2half2_rn(s0, s1);
        wcos[t] = __floats2half2_rn(c0, c1);
    }

    const __half* kbase = k + ((size_t)(b * L_ + chunk * KVCH)) * E_ + h * HD_;
    const __half* vbase = v + ((size_t)(b * L_ + chunk * KVCH)) * E_ + h * HD_;

    auto issue = [&](int slab, int buf) {
        uint32_t sK = smem_u32(Ksm[buf]);
        uint32_t sV = smem_u32(Vsm[buf]);
        #pragma unroll
        for (int j = 0; j < 4; j++) {
            int i = t + j * 256;            // 0..1023: first 512 = k, next = v
            int idx = i & 511;
            int row = idx >> 3, c = idx & 7;
            const __half* src = ((i >> 9) ? vbase : kbase)
                              + (size_t)(slab * 64 + row) * E_ + c * 8;
            uint32_t dst = ((i >> 9) ? sV : sK) + swz((uint32_t)row * 128 + c * 16);
            cp_async16(dst, src);
        }
        cp_commit();
    };

    float acc[9][4];
    #pragma unroll
    for (int n8 = 0; n8 < 9; n8++)
        #pragma unroll
        for (int r = 0; r < 4; r++) acc[n8][r] = 0.f;

    issue(0, 0);
    const uint32_t ONES = 0x3C003C00u;
    const int d0 = (wid & 3) * 16;

    #pragma unroll
    for (int slab = 0; slab < KVCH / 64; slab++) {     // 4
        if (slab + 1 < KVCH / 64) {
            issue(slab + 1, (slab + 1) & 1);
            cp_wait_group<1>();
        } else {
            cp_wait_group<0>();
        }
        __syncthreads();
        uint32_t sK = smem_u32(Ksm[slab & 1]);
        uint32_t sV = smem_u32(Vsm[slab & 1]);
        const __half2* wsel = (wid < 4) ? wsin : wcos;
        #pragma unroll
        for (int kk = 0; kk < 4; kk++) {
            uint32_t a[4], bf[4][4];
            ldmatrix_x4_trans(a, trans_addr(sK, kk, d0, lane));
            #pragma unroll
            for (int nb = 0; nb < 4; nb++)
                ldmatrix_x4_trans(bf[nb], trans_addr(sV, kk, nb * 16, lane));
            __half2 w0 = wsel[slab * 32 + kk * 8 + (lane & 3)];
            __half2 w1 = wsel[slab * 32 + kk * 8 + (lane & 3) + 4];
            __half2* ah = (__half2*)a;
            ah[0] = __hmul2(ah[0], w0);
            ah[1] = __hmul2(ah[1], w0);
            ah[2] = __hmul2(ah[2], w1);
            ah[3] = __hmul2(ah[3], w1);
            #pragma unroll
            for (int n8 = 0; n8 < 8; n8++)
                mma_fp16(acc[n8], a, bf[n8 >> 1][n8 & 1], bf[n8 >> 1][(n8 & 1) + 2]);
            mma_fp16(acc[8], a, ONES, ONES);
        }
        __syncthreads();
    }

    // epilogue: partial kv + ksum
    const int qr = lane >> 2, qc = (lane & 3) * 2;
    float* kvout = &g_kvp[((size_t)(chunk * BH_ + head)) * 128 * HD_];
    #pragma unroll
    for (int n8 = 0; n8 < 8; n8++) {
        int col = n8 * 8 + qc;
        *(float2*)&kvout[(wid * 16 + qr) * HD_ + col]     = make_float2(acc[n8][0], acc[n8][1]);
        *(float2*)&kvout[(wid * 16 + qr + 8) * HD_ + col] = make_float2(acc[n8][2], acc[n8][3]);
    }
    if ((lane & 3) == 0) {
        g_ksump[(chunk * BH_ + head) * 128 + wid * 16 + qr]     = acc[8][0];
        g_ksump[(chunk * BH_ + head) * 128 + wid * 16 + qr + 8] = acc[8][2];
    }
}

// Reduce partials; emit transposed fp16 kv: g_kvt[head][d>>6][m][d&63]
// grid (BH_, 8): slice covers 1024 of the 8192 elements per head
__global__ __launch_bounds__(256)
void kv_reduce()
{
    int head = blockIdx.x, slice = blockIdx.y;
    int t = threadIdx.x;
    int e = slice * 1024 + t;
    #pragma unroll
    for (int j = 0; j < 4; j++, e += 256) {
        int d = e >> 6, m = e & 63;
        float s = 0.f;
        #pragma unroll
        for (int c = 0; c < NCHUNK; c++)
            s += g_kvp[((size_t)(c * BH_ + head)) * 128 * HD_ + e];
        g_kvt[(((size_t)head * 2 + (d >> 6)) * 64 + m) * 64 + (d & 63)] = __float2half_rn(s);
    }
    if (slice == 0 && t < 128) {
        float s = 0.f;
        #pragma unroll
        for (int c = 0; c < NCHUNK; c++)
            s += g_ksump[(c * BH_ + head) * 128 + t];
        g_ksum[head * 128 + t] = s;
    }
}

// ================= attn via HMMA =================
// A = q_ fp16 1-term (2 slabs of k64), B = kvt single-term (2 slabs).
// Passes: (A0,B0)(A1,B1) = sum over d' of q_ * kv.
#define ATT_A_SM 32768            // 2 slabs * 128 rows * 128B
#define ATT_B_SM 16384            // 2 slabs * 64 rows * 128B
#define ATT_DSMEM (ATT_A_SM + ATT_B_SM + 128)

__global__ __launch_bounds__(256, 2)
void attn_hmma(const __half* __restrict__ q)
{
    extern __shared__ char dsm[];
    __shared__ float ss[128], cs[128], zs[128], ks_s[128];

    const int t = threadIdx.x;
    const int wid = t >> 5, lane = t & 31;
    const int ltile = blockIdx.x;           // 0..31
    const int head  = blockIdx.y;           // 0..63
    const int b = head / H_, h = head % H_;

    char* sm = (char*)((((uintptr_t)dsm) + 127) & ~(uintptr_t)127);
    uint32_t sA = smem_u32(sm);
    uint32_t sB = sA + ATT_A_SM;

    if (t < 128) {
        int l = ltile * 128 + t;
        float ang = (float)M_PI * 0.5f * (float)(l + 1) / (float)L_;
        sincosf(ang, &ss[t], &cs[t]);
        ks_s[t] = g_ksum[head * 128 + t];
    }

    {
        const __half* kvt = g_kvt + (size_t)head * 128 * 64;
        #pragma unroll
        for (int j = 0; j < 4; j++) {
            int i = t + j * 256;            // 0..1023 16B chunks
            int row = i >> 3, c = i & 7;    // 128 rows of 64 halves
            cp_async16(sB + swz((uint32_t)row * 128 + c * 16),
                       kvt + row * 64 + c * 8);
        }
        cp_commit();
    }
    __syncthreads();

    {
        const int l_loc = t >> 1;           // 0..127
        const int halfsel = t & 1;
        int lg = ltile * 128 + l_loc;
        const __half* qrow = q + ((size_t)(b * L_ + lg)) * E_ + h * HD_;
        float w = halfsel ? cs[l_loc] : ss[l_loc];
        float zpart = 0.f;
        char* aw = sm + halfsel * 16384;    // slab halfsel
        #pragma unroll 4
        for (int it = 0; it < 32; it++) {
            int dp = halfsel * 64 + 2 * it;
            float2 qq = __half22float2(*(const __half2*)&qrow[dp & 63]);
            float f0 = w * qq.x, f1 = w * qq.y;
            zpart += f0 * ks_s[dp] + f1 * ks_s[dp + 1];
            __half2 Hp = __floats2half2_rn(f0, f1);
            uint32_t off = swz((uint32_t)l_loc * 128 + (dp & 63) * 2);
            *(uint32_t*)(aw + off) = *(uint32_t*)&Hp;
        }
        zpart += __shfl_xor_sync(0xffffffffu, zpart, 1);
        if (!halfsel) zs[l_loc] = 1.f / fmaxf(zpart, EPS_);
    }

    cp_wait_group<0>();
    __syncthreads();

    const int wm = wid & 1;
    const int wn = wid >> 1;
    const int lrow = lane & 15;
    const int lhalf = (lane >> 4) * 16;

    float acc[4][2][4];
    #pragma unroll
    for (int mi = 0; mi < 4; mi++)
        #pragma unroll
        for (int hi = 0; hi < 2; hi++)
            #pragma unroll
            for (int r = 0; r < 4; r++) acc[mi][hi][r] = 0.f;

    #pragma unroll
    for (int p = 0; p < 2; p++) {
        uint32_t a_s = sA + p * 16384;
        uint32_t b_s = sB + p * 8192;
        #pragma unroll
        for (int kk = 0; kk < 4; kk++) {
            uint32_t a[4][4], bfr[4];
            #pragma unroll
            for (int mi = 0; mi < 4; mi++) {
                uint32_t off = (uint32_t)(wm * 64 + mi * 16 + lrow) * 128 + kk * 32 + lhalf;
                ldmatrix_x4(a[mi], a_s + swz(off));
            }
            {
                uint32_t off = (uint32_t)(wn * 16 + lrow) * 128 + kk * 32 + lhalf;
                ldmatrix_x4(bfr, b_s + swz(off));
            }
            #pragma unroll
            for (int mi = 0; mi < 4; mi++)
                #pragma unroll
                for (int hi = 0; hi < 2; hi++)
                    mma_fp16(acc[mi][hi], a[mi], bfr[hi], bfr[hi + 2]);
        }
    }

    const int qr = lane >> 2;
    const int qc = (lane & 3) * 2;
    #pragma unroll
    for (int mi = 0; mi < 4; mi++) {
        #pragma unroll
        for (int hi = 0; hi < 2; hi++) {
            #pragma unroll
            for (int r = 0; r < 2; r++) {
                int lloc = wm * 64 + mi * 16 + qr + r * 8;
                int n = wn * 16 + hi * 8 + qc;
                float z = zs[lloc];
                __half2 Hp = __floats2half2_rn(acc[mi][hi][r * 2 + 0] * z,
                                               acc[mi][hi][r * 2 + 1] * z);
                __half* ob = g_attn2 + ((size_t)(b * L_ + ltile * 128 + lloc)) * KTOT
                           + h * HD_ + n;
                *(uint32_t*)(ob) = *(uint32_t*)&Hp;
            }
        }
    }
}

// ================= launcher =================
extern "C" void kernel_launch(void* const* d_in, const int* in_sizes, int n_in,
                              void* d_out, int out_size)
{
    const float* x  = (const float*)d_in[0];
    const float* Wq = (const float*)d_in[1];
    const float* bq = (const float*)d_in[2];
    const float* Wk = (const float*)d_in[3];
    const float* bk = (const float*)d_in[4];
    const float* Wv = (const float*)d_in[5];
    const float* bv = (const float*)d_in[6];
    const float* Wo = (const float*)d_in[7];
    const float* bo = (const float*)d_in[8];
    float* out = (float*)d_out;

    __half *x2, *attn2, *w2, *qh, *kh, *vh;
    cudaGetSymbolAddress((void**)&x2,    g_x2);
    cudaGetSymbolAddress((void**)&attn2, g_attn2);
    cudaGetSymbolAddress((void**)&w2,    g_w2);
    cudaGetSymbolAddress((void**)&qh,    g_qh);
    cudaGetSymbolAddress((void**)&kh,    g_kh);
    cudaGetSymbolAddress((void**)&vh,    g_vh);
    __half* w2o = w2 + (size_t)3 * E_ * KTOT;

    cudaFuncSetAttribute(gemm_mma,  cudaFuncAttributeMaxDynamicSharedMemorySize, GEMM_DSMEM);
    cudaFuncSetAttribute(gemm_qkv,  cudaFuncAttributeMaxDynamicSharedMemorySize, GEMM_DSMEM);
    cudaFuncSetAttribute(attn_hmma, cudaFuncAttributeMaxDynamicSharedMemorySize, ATT_DSMEM);

    // one merged conversion launch: x + 4 weights
    convert_all<<<16384 + 4096, 256>>>(x, Wq, Wk, Wv, Wo, x2, w2);

    // merged QKV projection (fp16 outputs)
    gemm_qkv<<<dim3(3 * E_ / GBN, M_ / GBM), 256, GEMM_DSMEM>>>(
        x2, w2, bq, bk, bv, qh, kh, vh);

    kv_hmma<<<dim3(BH_, NCHUNK), 256>>>(kh, vh);
    kv_reduce<<<dim3(BH_, 8), 256>>>();
    attn_hmma<<<dim3(32, BH_), 256, ATT_DSMEM>>>(qh);

    gemm_mma<<<dim3(E_ / GBN, M_ / GBM), 256, GEMM_DSMEM>>>(attn2, w2o, bo, out);
}